// round 11
// baseline (speedup 1.0000x reference)
#include <cuda_runtime.h>
#include <math.h>

// ---------------- problem constants ----------------
#define BB   2
#define TT   2048
#define CCH  1024
#define NHQ  16
#define NKV  8
#define HD   64
#define WIN  512
#define HID  4096
#define MROWS (BB*TT)   // 4096

// ---------------- scratch (device globals; no allocs allowed) ----------------
__device__ float g_attn_in[MROWS*CCH];      // 16 MB
__device__ float g_q[BB*NHQ*TT*HD];         // 16 MB  (b,hq,t,d)
__device__ float g_k[BB*NKV*TT*HD];         //  8 MB
__device__ float g_v[BB*NKV*TT*HD];         //  8 MB
__device__ float g_O[MROWS*CCH];            // 16 MB  (b,t,hq,d)
__device__ float g_x1[MROWS*CCH];           // 16 MB
__device__ float g_mlp[MROWS*CCH];          // 16 MB
__device__ float g_gate[MROWS*HID];         // 64 MB
__device__ float g_h[MROWS*HID];            // 64 MB
__device__ float g_rowk[MROWS];
__device__ float g_rope_s[TT*32];
__device__ float g_rope_c[TT*32];
__device__ float g_wc[15*1024*1024];        // 60 MB: tf32-rounded weights

// weight offsets inside g_wc (floats)
#define OFF_QW 0
#define OFF_KW (OFF_QW + CCH*1024)
#define OFF_VW (OFF_KW + CCH*512)
#define OFF_OW (OFF_VW + CCH*512)
#define OFF_GW (OFF_OW + 1024*CCH)
#define OFF_UW (OFF_GW + CCH*HID)
#define OFF_DW (OFF_UW + CCH*HID)

// ---------------- helpers ----------------
__device__ __forceinline__ float tf32r(float f) {
    unsigned u;
    asm("cvt.rna.tf32.f32 %0, %1;" : "=r"(u) : "f"(f));
    return __uint_as_float(u);
}

__device__ __forceinline__ float blockReduceSum(float v) {
    __shared__ float sh[8];
    int lane = threadIdx.x & 31, wid = threadIdx.x >> 5;
    #pragma unroll
    for (int o = 16; o > 0; o >>= 1) v += __shfl_xor_sync(0xffffffffu, v, o);
    __syncthreads();
    if (lane == 0) sh[wid] = v;
    __syncthreads();
    if (wid == 0) {
        float r = (lane < 8) ? sh[lane] : 0.f;
        #pragma unroll
        for (int o = 4; o > 0; o >>= 1) r += __shfl_xor_sync(0xffffffffu, r, o);
        if (lane == 0) sh[0] = r;
    }
    __syncthreads();
    return sh[0];
}

// ---------------- tf32 weight pre-round ----------------
__global__ __launch_bounds__(256) void tf32cvt_k(const float* __restrict__ in,
                                                 float* __restrict__ out, int n4) {
    int i = blockIdx.x * 256 + threadIdx.x;
    if (i >= n4) return;
    float4 v = ((const float4*)in)[i];
    v.x = tf32r(v.x); v.y = tf32r(v.y); v.z = tf32r(v.z); v.w = tf32r(v.w);
    ((float4*)out)[i] = v;
}

// ---------------- RMSNorm (emits tf32-rounded output) ----------------
__global__ __launch_bounds__(256) void rmsnorm_k(const float* __restrict__ x,
                                                 const float* __restrict__ scale,
                                                 float* __restrict__ out) {
    int row = blockIdx.x;
    const float* xr = x + (size_t)row * CCH;
    float s = 0.f;
    for (int i = threadIdx.x; i < CCH; i += 256) { float v = xr[i]; s += v * v; }
    s = blockReduceSum(s);
    float inv = rsqrtf(s / CCH + 1e-6f);
    float* orow = out + (size_t)row * CCH;
    for (int i = threadIdx.x; i < CCH; i += 256)
        orow[i] = tf32r(xr[i] * inv * (1.f + scale[i]));
}

// ---------------- tf32 tensor-core GEMM, cp.async 3-stage ----------------
// CTA 128x128, BK=32, 8 warps (2x4), warp tile 64x32, m16n8k8.
// Inputs assumed pre-rounded to tf32 (raw bits copied; HW truncation is exact).
// mode 0: C = acc
// mode 1: head-major scatter (tf32-rounded stores)
// mode 2: C = acc + aux
// mode 3: C = acc * silu(aux)   (tf32-rounded stores)
#define APITCH 36
#define BPITCH 136
#define ASZ (128*APITCH)        // floats per A stage
#define BSZ (32*BPITCH)
#define STAGE (ASZ + BSZ)       // 8960 floats = 35840 B
#define NSTAGE 3
#define GEMM_SMEM (NSTAGE*STAGE*4)

__device__ __forceinline__ void cpa16(float* dst, const float* src) {
    unsigned d = (unsigned)__cvta_generic_to_shared(dst);
    asm volatile("cp.async.cg.shared.global [%0], [%1], 16;" :: "r"(d), "l"(src));
}

__device__ __forceinline__ void mma_tf32(float* c, const unsigned* a, const unsigned* b) {
    asm volatile(
        "mma.sync.aligned.m16n8k8.row.col.f32.tf32.tf32.f32 "
        "{%0,%1,%2,%3}, {%4,%5,%6,%7}, {%8,%9}, {%0,%1,%2,%3};"
        : "+f"(c[0]), "+f"(c[1]), "+f"(c[2]), "+f"(c[3])
        : "r"(a[0]), "r"(a[1]), "r"(a[2]), "r"(a[3]), "r"(b[0]), "r"(b[1]));
}

__global__ __launch_bounds__(256, 2) void tgemm_k(const float* __restrict__ A,
                                                  const float* __restrict__ B,
                                                  float* __restrict__ C,
                                                  int M, int N, int K,
                                                  int mode, const float* __restrict__ aux,
                                                  int Tdim, int nheads) {
    extern __shared__ float sm[];

    const int tid  = threadIdx.x;
    const int bx   = blockIdx.x, by = blockIdx.y;
    const int warp = tid >> 5, lane = tid & 31;
    const int wm = warp & 1, wn = warp >> 1;     // 2 x 4 warp grid
    const int mw = wm * 64, nw = wn * 32;
    const int grp = lane >> 2, qd = lane & 3;

    const float* Ab = A + (size_t)by * 128 * K;
    const float* Bb = B + (size_t)bx * 128;

    const int arow = tid >> 3;             // + i*32
    const int acol = (tid & 7) * 4;
    const int brow = tid >> 5;             // + i*8
    const int bcol = (tid & 31) * 4;

    float acc[4][4][4];
    #pragma unroll
    for (int mi = 0; mi < 4; mi++)
        #pragma unroll
        for (int ni = 0; ni < 4; ni++)
            #pragma unroll
            for (int r = 0; r < 4; r++) acc[mi][ni][r] = 0.f;

    const int nK = K >> 5;   // K/32, always >= 2 here

    // ---- issue loads for slab kt into stage st ----
    #define ISSUE(kt, st) do {                                                    \
        float* As_ = sm + (st) * STAGE;                                           \
        float* Bs_ = As_ + ASZ;                                                   \
        const float* Ag = Ab + (size_t)(kt) * 32;                                 \
        const float* Bg = Bb + (size_t)(kt) * 32 * N;                             \
        _Pragma("unroll")                                                         \
        for (int i_ = 0; i_ < 4; i_++) {                                          \
            int r_ = arow + i_ * 32;                                              \
            cpa16(&As_[r_ * APITCH + acol], Ag + (size_t)r_ * K + acol);          \
            int rb_ = brow + i_ * 8;                                              \
            cpa16(&Bs_[rb_ * BPITCH + bcol], Bg + (size_t)rb_ * N + bcol);        \
        }                                                                         \
    } while (0)

    ISSUE(0, 0);
    asm volatile("cp.async.commit_group;");
    ISSUE(1, 1);
    asm volatile("cp.async.commit_group;");

    for (int kt = 0; kt < nK; kt++) {
        asm volatile("cp.async.wait_group 1;");
        __syncthreads();
        const int st = kt % NSTAGE;
        if (kt + 2 < nK) {
            ISSUE(kt + 2, (kt + 2) % NSTAGE);
        }
        asm volatile("cp.async.commit_group;");

        const float* As_ = sm + st * STAGE;
        const float* Bs_ = As_ + ASZ;

        #pragma unroll
        for (int ks = 0; ks < 4; ks++) {
            const int kk = ks * 8;
            unsigned af[4][4], bf[4][2];
            #pragma unroll
            for (int mi = 0; mi < 4; mi++) {
                int r = mw + mi * 16;
                af[mi][0] = __float_as_uint(As_[(r + grp) * APITCH + kk + qd]);
                af[mi][1] = __float_as_uint(As_[(r + 8 + grp) * APITCH + kk + qd]);
                af[mi][2] = __float_as_uint(As_[(r + grp) * APITCH + kk + 4 + qd]);
                af[mi][3] = __float_as_uint(As_[(r + 8 + grp) * APITCH + kk + 4 + qd]);
            }
            #pragma unroll
            for (int ni = 0; ni < 4; ni++) {
                int c = nw + ni * 8;
                bf[ni][0] = __float_as_uint(Bs_[(kk + qd) * BPITCH + c + grp]);
                bf[ni][1] = __float_as_uint(Bs_[(kk + 4 + qd) * BPITCH + c + grp]);
            }
            #pragma unroll
            for (int mi = 0; mi < 4; mi++)
                #pragma unroll
                for (int ni = 0; ni < 4; ni++)
                    mma_tf32(acc[mi][ni], af[mi], bf[ni]);
        }
        __syncthreads();
    }

    // epilogue
    #pragma unroll
    for (int mi = 0; mi < 4; mi++) {
        #pragma unroll
        for (int ni = 0; ni < 4; ni++) {
            int row0 = by * 128 + mw + mi * 16 + grp;
            int col  = bx * 128 + nw + ni * 8 + qd * 2;
            #pragma unroll
            for (int half = 0; half < 2; half++) {
                int row = row0 + half * 8;
                float v0 = acc[mi][ni][half * 2 + 0];
                float v1 = acc[mi][ni][half * 2 + 1];
                if (mode == 0) {
                    *(float2*)&C[(size_t)row * N + col] = make_float2(v0, v1);
                } else if (mode == 1) {
                    int bi = row / Tdim, s = row % Tdim;
                    int hq = col >> 6, d = col & 63;
                    size_t base = (((size_t)(bi * nheads + hq)) * Tdim + s) * 64 + d;
                    *(float2*)&C[base] = make_float2(tf32r(v0), tf32r(v1));
                } else if (mode == 2) {
                    size_t idx = (size_t)row * N + col;
                    float2 a2 = *(const float2*)&aux[idx];
                    *(float2*)&C[idx] = make_float2(v0 + a2.x, v1 + a2.y);
                } else {
                    size_t idx = (size_t)row * N + col;
                    float2 g2 = *(const float2*)&aux[idx];
                    float s0 = g2.x / (1.f + __expf(-g2.x));
                    float s1 = g2.y / (1.f + __expf(-g2.y));
                    *(float2*)&C[idx] = make_float2(tf32r(v0 * s0), tf32r(v1 * s1));
                }
            }
        }
    }
    #undef ISSUE
}

// ---------------- RoPE table + apply (rounded output) ----------------
__global__ void rope_table_k() {
    int idx = blockIdx.x * 256 + threadIdx.x;   // TT*32 = 65536
    int i = idx & 31, t = idx >> 5;
    double freq = exp(-(double)i / 32.0 * 13.815510557964274);  // ln(1e6)
    double ang = (double)t * freq;
    g_rope_s[idx] = (float)sin(ang);
    g_rope_c[idx] = (float)cos(ang);
}

__global__ void rope_k(float* __restrict__ buf, int total /* BH*T*32 */) {
    int idx = blockIdx.x * blockDim.x + threadIdx.x;
    if (idx >= total) return;
    int i  = idx & 31;
    int t  = (idx >> 5) & (TT - 1);
    int bh = idx >> 16;
    int ti = (idx & 0xFFFF);
    float sn = g_rope_s[ti], cs = g_rope_c[ti];
    float* p = buf + ((size_t)bh * TT + t) * 64;
    float x1 = p[i], x2 = p[i + 32];
    p[i]      = tf32r(x1 * cs - x2 * sn);
    p[i + 32] = tf32r(x2 * cs + x1 * sn);
}

// ---------------- sliding-window flash attention ----------------
#define PITCH 65
__global__ __launch_bounds__(256) void attn_k(const float* __restrict__ q,
                                              const float* __restrict__ k,
                                              const float* __restrict__ v,
                                              float* __restrict__ O) {
    extern __shared__ float sma[];
    float* Qs = sma;                      // 64*65
    float* Ks = Qs + 64 * PITCH;
    float* Vs = Ks + 64 * PITCH;
    float* Ss = Vs + 64 * PITCH;
    float* m_s  = Ss + 64 * PITCH;
    float* l_s  = m_s + 64;
    float* al_s = l_s + 64;

    const int qt = blockIdx.x, hq = blockIdx.y, b = blockIdx.z;
    const int hk = hq & (NKV - 1);
    const int tid = threadIdx.x;
    const int q0 = qt * 64;
    const float* qb = q + (((size_t)(b * NHQ + hq)) * TT + q0) * 64;
    const float* kb = k + ((size_t)(b * NKV + hk)) * TT * 64;
    const float* vb = v + ((size_t)(b * NKV + hk)) * TT * 64;

    {
        int r = tid >> 2, cg = (tid & 3) * 16;
        #pragma unroll
        for (int g = 0; g < 16; g += 4) {
            float4 t4 = *(const float4*)(qb + (size_t)r * 64 + cg + g);
            Qs[r * PITCH + cg + g + 0] = t4.x; Qs[r * PITCH + cg + g + 1] = t4.y;
            Qs[r * PITCH + cg + g + 2] = t4.z; Qs[r * PITCH + cg + g + 3] = t4.w;
        }
    }
    if (tid < 64) { m_s[tid] = -1e30f; l_s[tid] = 0.f; }

    const int tr = tid >> 4, tc = tid & 15;
    const int r0 = tr * 4, c0 = tc * 4;
    float o[4][4];
    #pragma unroll
    for (int i = 0; i < 4; i++)
        #pragma unroll
        for (int j = 0; j < 4; j++) o[i][j] = 0.f;

    int kb_lo = max(0, q0 - (WIN - 1)) >> 6;
    for (int kbi = kb_lo; kbi <= qt; kbi++) {
        int j0 = kbi * 64;
        __syncthreads();
        {
            int r = tid >> 2, cg = (tid & 3) * 16;
            #pragma unroll
            for (int g = 0; g < 16; g += 4) {
                float4 t4 = *(const float4*)(kb + ((size_t)(j0 + r)) * 64 + cg + g);
                Ks[r * PITCH + cg + g + 0] = t4.x; Ks[r * PITCH + cg + g + 1] = t4.y;
                Ks[r * PITCH + cg + g + 2] = t4.z; Ks[r * PITCH + cg + g + 3] = t4.w;
                float4 u4 = *(const float4*)(vb + ((size_t)(j0 + r)) * 64 + cg + g);
                Vs[r * PITCH + cg + g + 0] = u4.x; Vs[r * PITCH + cg + g + 1] = u4.y;
                Vs[r * PITCH + cg + g + 2] = u4.z; Vs[r * PITCH + cg + g + 3] = u4.w;
            }
        }
        __syncthreads();

        float sreg[4][4];
        #pragma unroll
        for (int i = 0; i < 4; i++)
            #pragma unroll
            for (int j = 0; j < 4; j++) sreg[i][j] = 0.f;
        #pragma unroll 8
        for (int kk = 0; kk < 64; kk++) {
            float qv[4], kv[4];
            #pragma unroll
            for (int i = 0; i < 4; i++) qv[i] = Qs[(r0 + i) * PITCH + kk];
            #pragma unroll
            for (int j = 0; j < 4; j++) kv[j] = Ks[(c0 + j) * PITCH + kk];
            #pragma unroll
            for (int i = 0; i < 4; i++)
                #pragma unroll
                for (int j = 0; j < 4; j++) sreg[i][j] += qv[i] * kv[j];
        }
        #pragma unroll
        for (int i = 0; i < 4; i++) {
            int sa = q0 + r0 + i;
            #pragma unroll
            for (int j = 0; j < 4; j++) {
                int ja = j0 + c0 + j;
                float val = sreg[i][j] * 0.125f * 0.02f;
                float th;
                asm("tanh.approx.f32 %0, %1;" : "=f"(th) : "f"(val));
                val = 50.f * th;
                bool valid = (ja <= sa) && (sa - ja < WIN);
                Ss[(r0 + i) * PITCH + (c0 + j)] = valid ? val : -1e30f;
            }
        }
        __syncthreads();

        if (tid < 64) {
            float mold = m_s[tid];
            float mx = mold;
            float* srow = Ss + tid * PITCH;
            #pragma unroll 8
            for (int c2 = 0; c2 < 64; c2++) mx = fmaxf(mx, srow[c2]);
            if (mx < -1e29f) {
                al_s[tid] = 1.f;
                #pragma unroll 8
                for (int c2 = 0; c2 < 64; c2++) srow[c2] = 0.f;
            } else {
                float al = __expf(mold - mx);
                float ls = 0.f;
                #pragma unroll 8
                for (int c2 = 0; c2 < 64; c2++) {
                    float p = __expf(srow[c2] - mx);
                    srow[c2] = p; ls += p;
                }
                l_s[tid] = l_s[tid] * al + ls;
                m_s[tid] = mx;
                al_s[tid] = al;
            }
        }
        __syncthreads();

        #pragma unroll
        for (int i = 0; i < 4; i++) {
            float al = al_s[r0 + i];
            #pragma unroll
            for (int j = 0; j < 4; j++) o[i][j] *= al;
        }
        #pragma unroll 8
        for (int kk = 0; kk < 64; kk++) {
            float vv0 = Vs[kk * PITCH + c0 + 0];
            float vv1 = Vs[kk * PITCH + c0 + 1];
            float vv2 = Vs[kk * PITCH + c0 + 2];
            float vv3 = Vs[kk * PITCH + c0 + 3];
            #pragma unroll
            for (int i = 0; i < 4; i++) {
                float p = Ss[(r0 + i) * PITCH + kk];
                o[i][0] += p * vv0; o[i][1] += p * vv1;
                o[i][2] += p * vv2; o[i][3] += p * vv3;
            }
        }
    }

    #pragma unroll
    for (int i = 0; i < 4; i++) {
        float invl = 1.f / l_s[r0 + i];
        size_t base = ((size_t)(b * TT + q0 + r0 + i)) * CCH + hq * 64 + c0;
        #pragma unroll
        for (int j = 0; j < 4; j++) O[base + j] = tf32r(o[i][j] * invl);
    }
}

// ---------------- excess kurtosis ----------------
__global__ __launch_bounds__(256) void kurt_rows_k(const float* __restrict__ x,
                                                   float* __restrict__ rowk) {
    int row = blockIdx.x;
    const float* xr = x + (size_t)row * CCH;
    float s = 0.f;
    for (int i = threadIdx.x; i < CCH; i += 256) s += xr[i];
    s = blockReduceSum(s);
    float mean = s / CCH;
    float a2 = 0.f, a4 = 0.f;
    for (int i = threadIdx.x; i < CCH; i += 256) {
        float d = xr[i] - mean; float d2 = d * d;
        a2 += d2; a4 += d2 * d2;
    }
    a2 = blockReduceSum(a2);
    a4 = blockReduceSum(a4);
    if (threadIdx.x == 0) {
        float var = a2 / CCH, m4 = a4 / CCH;
        float kurt = m4 / (var * var + 1e-6f) - 3.f;
        rowk[row] = fmaxf(kurt, 0.f);
    }
}

__global__ __launch_bounds__(256) void kurt_final_k(const float* __restrict__ rowk,
                                                    const float* __restrict__ ksum,
                                                    float* __restrict__ outp) {
    float s = 0.f;
    for (int i = threadIdx.x; i < MROWS; i += 256) s += rowk[i];
    s = blockReduceSum(s);
    if (threadIdx.x == 0) outp[0] = s + ksum[0];
}

// ---------------- launcher ----------------
extern "C" void kernel_launch(void* const* d_in, const int* in_sizes, int n_in,
                              void* d_out, int out_size) {
    (void)in_sizes; (void)n_in; (void)out_size;
    const float* x    = (const float*)d_in[0];
    const float* ksum = (const float*)d_in[1];
    const float* rms1 = (const float*)d_in[2];
    const float* qw   = (const float*)d_in[3];
    const float* kw   = (const float*)d_in[4];
    const float* vw   = (const float*)d_in[5];
    const float* ow   = (const float*)d_in[6];
    const float* rms2 = (const float*)d_in[7];
    const float* gw   = (const float*)d_in[8];
    const float* uw   = (const float*)d_in[9];
    const float* dw   = (const float*)d_in[10];
    float* out = (float*)d_out;

    float *attn_in, *qb, *kb, *vb, *Ob, *x1, *mlp, *gate, *hb, *rowk, *wc;
    cudaGetSymbolAddress((void**)&attn_in, g_attn_in);
    cudaGetSymbolAddress((void**)&qb,   g_q);
    cudaGetSymbolAddress((void**)&kb,   g_k);
    cudaGetSymbolAddress((void**)&vb,   g_v);
    cudaGetSymbolAddress((void**)&Ob,   g_O);
    cudaGetSymbolAddress((void**)&x1,   g_x1);
    cudaGetSymbolAddress((void**)&mlp,  g_mlp);
    cudaGetSymbolAddress((void**)&gate, g_gate);
    cudaGetSymbolAddress((void**)&hb,   g_h);
    cudaGetSymbolAddress((void**)&rowk, g_rowk);
    cudaGetSymbolAddress((void**)&wc,   g_wc);

    float* qw2 = wc + OFF_QW;  float* kw2 = wc + OFF_KW;
    float* vw2 = wc + OFF_VW;  float* ow2 = wc + OFF_OW;
    float* gw2 = wc + OFF_GW;  float* uw2 = wc + OFF_UW;
    float* dw2 = wc + OFF_DW;

    cudaFuncSetAttribute(tgemm_k, cudaFuncAttributeMaxDynamicSharedMemorySize, GEMM_SMEM);

    // 0) weight tf32 pre-round + rope table
    tf32cvt_k<<<(CCH*1024/4 + 255)/256, 256>>>(qw, qw2, CCH*1024/4);
    tf32cvt_k<<<(CCH*512/4  + 255)/256, 256>>>(kw, kw2, CCH*512/4);
    tf32cvt_k<<<(CCH*512/4  + 255)/256, 256>>>(vw, vw2, CCH*512/4);
    tf32cvt_k<<<(1024*CCH/4 + 255)/256, 256>>>(ow, ow2, 1024*CCH/4);
    tf32cvt_k<<<(CCH*HID/4  + 255)/256, 256>>>(gw, gw2, CCH*HID/4);
    tf32cvt_k<<<(CCH*HID/4  + 255)/256, 256>>>(uw, uw2, CCH*HID/4);
    tf32cvt_k<<<(HID*CCH/4  + 255)/256, 256>>>(dw, dw2, HID*CCH/4);
    rope_table_k<<<(TT * 32) / 256, 256>>>();

    // 1) rmsnorm1 (tf32-rounded out)
    rmsnorm_k<<<MROWS, 256>>>(x, rms1, attn_in);

    // 2) QKV projections
    dim3 gq(1024 / 128, MROWS / 128);
    tgemm_k<<<gq, 256, GEMM_SMEM>>>(attn_in, qw2, qb, MROWS, 1024, CCH, 1, nullptr, TT, NHQ);
    dim3 gkv(512 / 128, MROWS / 128);
    tgemm_k<<<gkv, 256, GEMM_SMEM>>>(attn_in, kw2, kb, MROWS, 512, CCH, 1, nullptr, TT, NKV);
    tgemm_k<<<gkv, 256, GEMM_SMEM>>>(attn_in, vw2, vb, MROWS, 512, CCH, 1, nullptr, TT, NKV);

    // 3) RoPE
    int nq = BB * NHQ * TT * 32;
    rope_k<<<nq / 256, 256>>>(qb, nq);
    int nk = BB * NKV * TT * 32;
    rope_k<<<nk / 256, 256>>>(kb, nk);

    // 4) attention
    int smemAttn = (4 * 64 * PITCH + 3 * 64) * (int)sizeof(float);
    cudaFuncSetAttribute(attn_k, cudaFuncAttributeMaxDynamicSharedMemorySize, smemAttn);
    dim3 ga(TT / 64, NHQ, BB);
    attn_k<<<ga, 256, smemAttn>>>(qb, kb, vb, Ob);

    // 5) out projection + residual
    dim3 go(CCH / 128, MROWS / 128);
    tgemm_k<<<go, 256, GEMM_SMEM>>>(Ob, ow2, x1, MROWS, CCH, 1024, 2, x, 0, 0);

    // 6) rmsnorm2
    rmsnorm_k<<<MROWS, 256>>>(x1, rms2, mlp);

    // 7) MLP
    dim3 gg(HID / 128, MROWS / 128);
    tgemm_k<<<gg, 256, GEMM_SMEM>>>(mlp, gw2, gate, MROWS, HID, CCH, 0, nullptr, 0, 0);
    tgemm_k<<<gg, 256, GEMM_SMEM>>>(mlp, uw2, hb,   MROWS, HID, CCH, 3, gate,    0, 0);
    dim3 gd(CCH / 128, MROWS / 128);
    tgemm_k<<<gd, 256, GEMM_SMEM>>>(hb, dw2, out, MROWS, CCH, HID, 2, x1, 0, 0);

    // 8) kurtosis
    kurt_rows_k<<<MROWS, 256>>>(out, rowk);
    kurt_final_k<<<1, 256>>>(rowk, ksum, out + (size_t)MROWS * CCH);
}

// round 12
// speedup vs baseline: 1.0032x; 1.0032x over previous
#include <cuda_runtime.h>
#include <math.h>

// ---------------- problem constants ----------------
#define BB   2
#define TT   2048
#define CCH  1024
#define NHQ  16
#define NKV  8
#define HD   64
#define WIN  512
#define HID  4096
#define MROWS (BB*TT)   // 4096

// ---------------- scratch (device globals; no allocs allowed) ----------------
__device__ float g_attn_in[MROWS*CCH];      // 16 MB
__device__ float g_q[BB*NHQ*TT*HD];         // 16 MB  (b,hq,t,d)
__device__ float g_k[BB*NKV*TT*HD];         //  8 MB
__device__ float g_v[BB*NKV*TT*HD];         //  8 MB
__device__ float g_O[MROWS*CCH];            // 16 MB  (b,t,hq,d)
__device__ float g_x1[MROWS*CCH];           // 16 MB
__device__ float g_mlp[MROWS*CCH];          // 16 MB
__device__ float g_gate[MROWS*HID];         // 64 MB
__device__ float g_h[MROWS*HID];            // 64 MB
__device__ float g_rowk[MROWS];
__device__ float g_rope_s[TT*32];
__device__ float g_rope_c[TT*32];
__device__ float g_wc[15*1024*1024];        // 60 MB: tf32-rounded weights

// weight offsets inside g_wc (floats)
#define OFF_QW 0
#define OFF_KW (OFF_QW + CCH*1024)
#define OFF_VW (OFF_KW + CCH*512)
#define OFF_OW (OFF_VW + CCH*512)
#define OFF_GW (OFF_OW + 1024*CCH)
#define OFF_UW (OFF_GW + CCH*HID)
#define OFF_DW (OFF_UW + CCH*HID)

// ---------------- helpers ----------------
__device__ __forceinline__ float tf32r(float f) {
    unsigned u;
    asm("cvt.rna.tf32.f32 %0, %1;" : "=r"(u) : "f"(f));
    return __uint_as_float(u);
}

__device__ __forceinline__ float blockReduceSum(float v) {
    __shared__ float sh[8];
    int lane = threadIdx.x & 31, wid = threadIdx.x >> 5;
    #pragma unroll
    for (int o = 16; o > 0; o >>= 1) v += __shfl_xor_sync(0xffffffffu, v, o);
    __syncthreads();
    if (lane == 0) sh[wid] = v;
    __syncthreads();
    if (wid == 0) {
        float r = (lane < 8) ? sh[lane] : 0.f;
        #pragma unroll
        for (int o = 4; o > 0; o >>= 1) r += __shfl_xor_sync(0xffffffffu, r, o);
        if (lane == 0) sh[0] = r;
    }
    __syncthreads();
    return sh[0];
}

// ---------------- tf32 weight pre-round ----------------
__global__ __launch_bounds__(256) void tf32cvt_k(const float* __restrict__ in,
                                                 float* __restrict__ out, int n4) {
    int i = blockIdx.x * 256 + threadIdx.x;
    if (i >= n4) return;
    float4 v = ((const float4*)in)[i];
    v.x = tf32r(v.x); v.y = tf32r(v.y); v.z = tf32r(v.z); v.w = tf32r(v.w);
    ((float4*)out)[i] = v;
}

// ---------------- RMSNorm (emits tf32-rounded output) ----------------
__global__ __launch_bounds__(256) void rmsnorm_k(const float* __restrict__ x,
                                                 const float* __restrict__ scale,
                                                 float* __restrict__ out) {
    int row = blockIdx.x;
    const float* xr = x + (size_t)row * CCH;
    float s = 0.f;
    for (int i = threadIdx.x; i < CCH; i += 256) { float v = xr[i]; s += v * v; }
    s = blockReduceSum(s);
    float inv = rsqrtf(s / CCH + 1e-6f);
    float* orow = out + (size_t)row * CCH;
    for (int i = threadIdx.x; i < CCH; i += 256)
        orow[i] = tf32r(xr[i] * inv * (1.f + scale[i]));
}

// ---------------- tf32 tensor-core GEMM, cp.async 3-stage ----------------
// CTA 128x128, BK=32, 8 warps (2x4), warp tile 64x32, m16n8k8.
// Inputs assumed pre-rounded to tf32 (raw bits copied; HW truncation is exact).
// mode 0: C = acc
// mode 1: head-major scatter (tf32-rounded stores)
// mode 2: C = acc + aux
// mode 3: C = acc * silu(aux)   (tf32-rounded stores)
#define APITCH 36
#define BPITCH 136
#define ASZ (128*APITCH)        // floats per A stage
#define BSZ (32*BPITCH)
#define STAGE (ASZ + BSZ)       // 8960 floats = 35840 B
#define NSTAGE 3
#define GEMM_SMEM (NSTAGE*STAGE*4)

__device__ __forceinline__ void cpa16(float* dst, const float* src) {
    unsigned d = (unsigned)__cvta_generic_to_shared(dst);
    asm volatile("cp.async.cg.shared.global [%0], [%1], 16;" :: "r"(d), "l"(src));
}

__device__ __forceinline__ void mma_tf32(float* c, const unsigned* a, const unsigned* b) {
    asm volatile(
        "mma.sync.aligned.m16n8k8.row.col.f32.tf32.tf32.f32 "
        "{%0,%1,%2,%3}, {%4,%5,%6,%7}, {%8,%9}, {%0,%1,%2,%3};"
        : "+f"(c[0]), "+f"(c[1]), "+f"(c[2]), "+f"(c[3])
        : "r"(a[0]), "r"(a[1]), "r"(a[2]), "r"(a[3]), "r"(b[0]), "r"(b[1]));
}

__global__ __launch_bounds__(256, 2) void tgemm_k(const float* __restrict__ A,
                                                  const float* __restrict__ B,
                                                  float* __restrict__ C,
                                                  int M, int N, int K,
                                                  int mode, const float* __restrict__ aux,
                                                  int Tdim, int nheads) {
    extern __shared__ float sm[];

    const int tid  = threadIdx.x;
    const int bx   = blockIdx.x, by = blockIdx.y;
    const int warp = tid >> 5, lane = tid & 31;
    const int wm = warp & 1, wn = warp >> 1;     // 2 x 4 warp grid
    const int mw = wm * 64, nw = wn * 32;
    const int grp = lane >> 2, qd = lane & 3;

    const float* Ab = A + (size_t)by * 128 * K;
    const float* Bb = B + (size_t)bx * 128;

    const int arow = tid >> 3;             // + i*32
    const int acol = (tid & 7) * 4;
    const int brow = tid >> 5;             // + i*8
    const int bcol = (tid & 31) * 4;

    float acc[4][4][4];
    #pragma unroll
    for (int mi = 0; mi < 4; mi++)
        #pragma unroll
        for (int ni = 0; ni < 4; ni++)
            #pragma unroll
            for (int r = 0; r < 4; r++) acc[mi][ni][r] = 0.f;

    const int nK = K >> 5;   // K/32, always >= 2 here

    // ---- issue loads for slab kt into stage st ----
    #define ISSUE(kt, st) do {                                                    \
        float* As_ = sm + (st) * STAGE;                                           \
        float* Bs_ = As_ + ASZ;                                                   \
        const float* Ag = Ab + (size_t)(kt) * 32;                                 \
        const float* Bg = Bb + (size_t)(kt) * 32 * N;                             \
        _Pragma("unroll")                                                         \
        for (int i_ = 0; i_ < 4; i_++) {                                          \
            int r_ = arow + i_ * 32;                                              \
            cpa16(&As_[r_ * APITCH + acol], Ag + (size_t)r_ * K + acol);          \
            int rb_ = brow + i_ * 8;                                              \
            cpa16(&Bs_[rb_ * BPITCH + bcol], Bg + (size_t)rb_ * N + bcol);        \
        }                                                                         \
    } while (0)

    ISSUE(0, 0);
    asm volatile("cp.async.commit_group;");
    ISSUE(1, 1);
    asm volatile("cp.async.commit_group;");

    for (int kt = 0; kt < nK; kt++) {
        asm volatile("cp.async.wait_group 1;");
        __syncthreads();
        const int st = kt % NSTAGE;
        if (kt + 2 < nK) {
            ISSUE(kt + 2, (kt + 2) % NSTAGE);
        }
        asm volatile("cp.async.commit_group;");

        const float* As_ = sm + st * STAGE;
        const float* Bs_ = As_ + ASZ;

        #pragma unroll
        for (int ks = 0; ks < 4; ks++) {
            const int kk = ks * 8;
            unsigned af[4][4], bf[4][2];
            #pragma unroll
            for (int mi = 0; mi < 4; mi++) {
                int r = mw + mi * 16;
                af[mi][0] = __float_as_uint(As_[(r + grp) * APITCH + kk + qd]);
                af[mi][1] = __float_as_uint(As_[(r + 8 + grp) * APITCH + kk + qd]);
                af[mi][2] = __float_as_uint(As_[(r + grp) * APITCH + kk + 4 + qd]);
                af[mi][3] = __float_as_uint(As_[(r + 8 + grp) * APITCH + kk + 4 + qd]);
            }
            #pragma unroll
            for (int ni = 0; ni < 4; ni++) {
                int c = nw + ni * 8;
                bf[ni][0] = __float_as_uint(Bs_[(kk + qd) * BPITCH + c + grp]);
                bf[ni][1] = __float_as_uint(Bs_[(kk + 4 + qd) * BPITCH + c + grp]);
            }
            #pragma unroll
            for (int mi = 0; mi < 4; mi++)
                #pragma unroll
                for (int ni = 0; ni < 4; ni++)
                    mma_tf32(acc[mi][ni], af[mi], bf[ni]);
        }
        __syncthreads();
    }

    // epilogue
    #pragma unroll
    for (int mi = 0; mi < 4; mi++) {
        #pragma unroll
        for (int ni = 0; ni < 4; ni++) {
            int row0 = by * 128 + mw + mi * 16 + grp;
            int col  = bx * 128 + nw + ni * 8 + qd * 2;
            #pragma unroll
            for (int half = 0; half < 2; half++) {
                int row = row0 + half * 8;
                float v0 = acc[mi][ni][half * 2 + 0];
                float v1 = acc[mi][ni][half * 2 + 1];
                if (mode == 0) {
                    *(float2*)&C[(size_t)row * N + col] = make_float2(v0, v1);
                } else if (mode == 1) {
                    int bi = row / Tdim, s = row % Tdim;
                    int hq = col >> 6, d = col & 63;
                    size_t base = (((size_t)(bi * nheads + hq)) * Tdim + s) * 64 + d;
                    *(float2*)&C[base] = make_float2(tf32r(v0), tf32r(v1));
                } else if (mode == 2) {
                    size_t idx = (size_t)row * N + col;
                    float2 a2 = *(const float2*)&aux[idx];
                    *(float2*)&C[idx] = make_float2(v0 + a2.x, v1 + a2.y);
                } else {
                    size_t idx = (size_t)row * N + col;
                    float2 g2 = *(const float2*)&aux[idx];
                    float s0 = g2.x / (1.f + __expf(-g2.x));
                    float s1 = g2.y / (1.f + __expf(-g2.y));
                    *(float2*)&C[idx] = make_float2(tf32r(v0 * s0), tf32r(v1 * s1));
                }
            }
        }
    }
    #undef ISSUE
}

// ---------------- RoPE table + apply (rounded output) ----------------
__global__ void rope_table_k() {
    int idx = blockIdx.x * 256 + threadIdx.x;   // TT*32 = 65536
    int i = idx & 31, t = idx >> 5;
    double freq = exp(-(double)i / 32.0 * 13.815510557964274);  // ln(1e6)
    double ang = (double)t * freq;
    g_rope_s[idx] = (float)sin(ang);
    g_rope_c[idx] = (float)cos(ang);
}

__global__ void rope_k(float* __restrict__ buf, int total /* BH*T*32 */) {
    int idx = blockIdx.x * blockDim.x + threadIdx.x;
    if (idx >= total) return;
    int i  = idx & 31;
    int t  = (idx >> 5) & (TT - 1);
    int bh = idx >> 16;
    int ti = (idx & 0xFFFF);
    float sn = g_rope_s[ti], cs = g_rope_c[ti];
    float* p = buf + ((size_t)bh * TT + t) * 64;
    float x1 = p[i], x2 = p[i + 32];
    p[i]      = tf32r(x1 * cs - x2 * sn);
    p[i + 32] = tf32r(x2 * cs + x1 * sn);
}

// ---------------- sliding-window flash attention ----------------
#define PITCH 65
__global__ __launch_bounds__(256) void attn_k(const float* __restrict__ q,
                                              const float* __restrict__ k,
                                              const float* __restrict__ v,
                                              float* __restrict__ O) {
    extern __shared__ float sma[];
    float* Qs = sma;                      // 64*65
    float* Ks = Qs + 64 * PITCH;
    float* Vs = Ks + 64 * PITCH;
    float* Ss = Vs + 64 * PITCH;
    float* m_s  = Ss + 64 * PITCH;
    float* l_s  = m_s + 64;
    float* al_s = l_s + 64;

    const int qt = blockIdx.x, hq = blockIdx.y, b = blockIdx.z;
    const int hk = hq & (NKV - 1);
    const int tid = threadIdx.x;
    const int q0 = qt * 64;
    const float* qb = q + (((size_t)(b * NHQ + hq)) * TT + q0) * 64;
    const float* kb = k + ((size_t)(b * NKV + hk)) * TT * 64;
    const float* vb = v + ((size_t)(b * NKV + hk)) * TT * 64;

    {
        int r = tid >> 2, cg = (tid & 3) * 16;
        #pragma unroll
        for (int g = 0; g < 16; g += 4) {
            float4 t4 = *(const float4*)(qb + (size_t)r * 64 + cg + g);
            Qs[r * PITCH + cg + g + 0] = t4.x; Qs[r * PITCH + cg + g + 1] = t4.y;
            Qs[r * PITCH + cg + g + 2] = t4.z; Qs[r * PITCH + cg + g + 3] = t4.w;
        }
    }
    if (tid < 64) { m_s[tid] = -1e30f; l_s[tid] = 0.f; }

    const int tr = tid >> 4, tc = tid & 15;
    const int r0 = tr * 4, c0 = tc * 4;
    float o[4][4];
    #pragma unroll
    for (int i = 0; i < 4; i++)
        #pragma unroll
        for (int j = 0; j < 4; j++) o[i][j] = 0.f;

    int kb_lo = max(0, q0 - (WIN - 1)) >> 6;
    for (int kbi = kb_lo; kbi <= qt; kbi++) {
        int j0 = kbi * 64;
        __syncthreads();
        {
            int r = tid >> 2, cg = (tid & 3) * 16;
            #pragma unroll
            for (int g = 0; g < 16; g += 4) {
                float4 t4 = *(const float4*)(kb + ((size_t)(j0 + r)) * 64 + cg + g);
                Ks[r * PITCH + cg + g + 0] = t4.x; Ks[r * PITCH + cg + g + 1] = t4.y;
                Ks[r * PITCH + cg + g + 2] = t4.z; Ks[r * PITCH + cg + g + 3] = t4.w;
                float4 u4 = *(const float4*)(vb + ((size_t)(j0 + r)) * 64 + cg + g);
                Vs[r * PITCH + cg + g + 0] = u4.x; Vs[r * PITCH + cg + g + 1] = u4.y;
                Vs[r * PITCH + cg + g + 2] = u4.z; Vs[r * PITCH + cg + g + 3] = u4.w;
            }
        }
        __syncthreads();

        float sreg[4][4];
        #pragma unroll
        for (int i = 0; i < 4; i++)
            #pragma unroll
            for (int j = 0; j < 4; j++) sreg[i][j] = 0.f;
        #pragma unroll 8
        for (int kk = 0; kk < 64; kk++) {
            float qv[4], kv[4];
            #pragma unroll
            for (int i = 0; i < 4; i++) qv[i] = Qs[(r0 + i) * PITCH + kk];
            #pragma unroll
            for (int j = 0; j < 4; j++) kv[j] = Ks[(c0 + j) * PITCH + kk];
            #pragma unroll
            for (int i = 0; i < 4; i++)
                #pragma unroll
                for (int j = 0; j < 4; j++) sreg[i][j] += qv[i] * kv[j];
        }
        #pragma unroll
        for (int i = 0; i < 4; i++) {
            int sa = q0 + r0 + i;
            #pragma unroll
            for (int j = 0; j < 4; j++) {
                int ja = j0 + c0 + j;
                float val = sreg[i][j] * 0.125f * 0.02f;
                float th;
                asm("tanh.approx.f32 %0, %1;" : "=f"(th) : "f"(val));
                val = 50.f * th;
                bool valid = (ja <= sa) && (sa - ja < WIN);
                Ss[(r0 + i) * PITCH + (c0 + j)] = valid ? val : -1e30f;
            }
        }
        __syncthreads();

        if (tid < 64) {
            float mold = m_s[tid];
            float mx = mold;
            float* srow = Ss + tid * PITCH;
            #pragma unroll 8
            for (int c2 = 0; c2 < 64; c2++) mx = fmaxf(mx, srow[c2]);
            if (mx < -1e29f) {
                al_s[tid] = 1.f;
                #pragma unroll 8
                for (int c2 = 0; c2 < 64; c2++) srow[c2] = 0.f;
            } else {
                float al = __expf(mold - mx);
                float ls = 0.f;
                #pragma unroll 8
                for (int c2 = 0; c2 < 64; c2++) {
                    float p = __expf(srow[c2] - mx);
                    srow[c2] = p; ls += p;
                }
                l_s[tid] = l_s[tid] * al + ls;
                m_s[tid] = mx;
                al_s[tid] = al;
            }
        }
        __syncthreads();

        #pragma unroll
        for (int i = 0; i < 4; i++) {
            float al = al_s[r0 + i];
            #pragma unroll
            for (int j = 0; j < 4; j++) o[i][j] *= al;
        }
        #pragma unroll 8
        for (int kk = 0; kk < 64; kk++) {
            float vv0 = Vs[kk * PITCH + c0 + 0];
            float vv1 = Vs[kk * PITCH + c0 + 1];
            float vv2 = Vs[kk * PITCH + c0 + 2];
            float vv3 = Vs[kk * PITCH + c0 + 3];
            #pragma unroll
            for (int i = 0; i < 4; i++) {
                float p = Ss[(r0 + i) * PITCH + kk];
                o[i][0] += p * vv0; o[i][1] += p * vv1;
                o[i][2] += p * vv2; o[i][3] += p * vv3;
            }
        }
    }

    #pragma unroll
    for (int i = 0; i < 4; i++) {
        float invl = 1.f / l_s[r0 + i];
        size_t base = ((size_t)(b * TT + q0 + r0 + i)) * CCH + hq * 64 + c0;
        #pragma unroll
        for (int j = 0; j < 4; j++) O[base + j] = tf32r(o[i][j] * invl);
    }
}

// ---------------- excess kurtosis ----------------
__global__ __launch_bounds__(256) void kurt_rows_k(const float* __restrict__ x,
                                                   float* __restrict__ rowk) {
    int row = blockIdx.x;
    const float* xr = x + (size_t)row * CCH;
    float s = 0.f;
    for (int i = threadIdx.x; i < CCH; i += 256) s += xr[i];
    s = blockReduceSum(s);
    float mean = s / CCH;
    float a2 = 0.f, a4 = 0.f;
    for (int i = threadIdx.x; i < CCH; i += 256) {
        float d = xr[i] - mean; float d2 = d * d;
        a2 += d2; a4 += d2 * d2;
    }
    a2 = blockReduceSum(a2);
    a4 = blockReduceSum(a4);
    if (threadIdx.x == 0) {
        float var = a2 / CCH, m4 = a4 / CCH;
        float kurt = m4 / (var * var + 1e-6f) - 3.f;
        rowk[row] = fmaxf(kurt, 0.f);
    }
}

__global__ __launch_bounds__(256) void kurt_final_k(const float* __restrict__ rowk,
                                                    const float* __restrict__ ksum,
                                                    float* __restrict__ outp) {
    float s = 0.f;
    for (int i = threadIdx.x; i < MROWS; i += 256) s += rowk[i];
    s = blockReduceSum(s);
    if (threadIdx.x == 0) outp[0] = s + ksum[0];
}

// ---------------- launcher ----------------
extern "C" void kernel_launch(void* const* d_in, const int* in_sizes, int n_in,
                              void* d_out, int out_size) {
    (void)in_sizes; (void)n_in; (void)out_size;
    const float* x    = (const float*)d_in[0];
    const float* ksum = (const float*)d_in[1];
    const float* rms1 = (const float*)d_in[2];
    const float* qw   = (const float*)d_in[3];
    const float* kw   = (const float*)d_in[4];
    const float* vw   = (const float*)d_in[5];
    const float* ow   = (const float*)d_in[6];
    const float* rms2 = (const float*)d_in[7];
    const float* gw   = (const float*)d_in[8];
    const float* uw   = (const float*)d_in[9];
    const float* dw   = (const float*)d_in[10];
    float* out = (float*)d_out;

    float *attn_in, *qb, *kb, *vb, *Ob, *x1, *mlp, *gate, *hb, *rowk, *wc;
    cudaGetSymbolAddress((void**)&attn_in, g_attn_in);
    cudaGetSymbolAddress((void**)&qb,   g_q);
    cudaGetSymbolAddress((void**)&kb,   g_k);
    cudaGetSymbolAddress((void**)&vb,   g_v);
    cudaGetSymbolAddress((void**)&Ob,   g_O);
    cudaGetSymbolAddress((void**)&x1,   g_x1);
    cudaGetSymbolAddress((void**)&mlp,  g_mlp);
    cudaGetSymbolAddress((void**)&gate, g_gate);
    cudaGetSymbolAddress((void**)&hb,   g_h);
    cudaGetSymbolAddress((void**)&rowk, g_rowk);
    cudaGetSymbolAddress((void**)&wc,   g_wc);

    float* qw2 = wc + OFF_QW;  float* kw2 = wc + OFF_KW;
    float* vw2 = wc + OFF_VW;  float* ow2 = wc + OFF_OW;
    float* gw2 = wc + OFF_GW;  float* uw2 = wc + OFF_UW;
    float* dw2 = wc + OFF_DW;

    cudaFuncSetAttribute(tgemm_k, cudaFuncAttributeMaxDynamicSharedMemorySize, GEMM_SMEM);

    // 0) weight tf32 pre-round + rope table
    tf32cvt_k<<<(CCH*1024/4 + 255)/256, 256>>>(qw, qw2, CCH*1024/4);
    tf32cvt_k<<<(CCH*512/4  + 255)/256, 256>>>(kw, kw2, CCH*512/4);
    tf32cvt_k<<<(CCH*512/4  + 255)/256, 256>>>(vw, vw2, CCH*512/4);
    tf32cvt_k<<<(1024*CCH/4 + 255)/256, 256>>>(ow, ow2, 1024*CCH/4);
    tf32cvt_k<<<(CCH*HID/4  + 255)/256, 256>>>(gw, gw2, CCH*HID/4);
    tf32cvt_k<<<(CCH*HID/4  + 255)/256, 256>>>(uw, uw2, CCH*HID/4);
    tf32cvt_k<<<(HID*CCH/4  + 255)/256, 256>>>(dw, dw2, HID*CCH/4);
    rope_table_k<<<(TT * 32) / 256, 256>>>();

    // 1) rmsnorm1 (tf32-rounded out)
    rmsnorm_k<<<MROWS, 256>>>(x, rms1, attn_in);

    // 2) QKV projections
    dim3 gq(1024 / 128, MROWS / 128);
    tgemm_k<<<gq, 256, GEMM_SMEM>>>(attn_in, qw2, qb, MROWS, 1024, CCH, 1, nullptr, TT, NHQ);
    dim3 gkv(512 / 128, MROWS / 128);
    tgemm_k<<<gkv, 256, GEMM_SMEM>>>(attn_in, kw2, kb, MROWS, 512, CCH, 1, nullptr, TT, NKV);
    tgemm_k<<<gkv, 256, GEMM_SMEM>>>(attn_in, vw2, vb, MROWS, 512, CCH, 1, nullptr, TT, NKV);

    // 3) RoPE
    int nq = BB * NHQ * TT * 32;
    rope_k<<<nq / 256, 256>>>(qb, nq);
    int nk = BB * NKV * TT * 32;
    rope_k<<<nk / 256, 256>>>(kb, nk);

    // 4) attention
    int smemAttn = (4 * 64 * PITCH + 3 * 64) * (int)sizeof(float);
    cudaFuncSetAttribute(attn_k, cudaFuncAttributeMaxDynamicSharedMemorySize, smemAttn);
    dim3 ga(TT / 64, NHQ, BB);
    attn_k<<<ga, 256, smemAttn>>>(qb, kb, vb, Ob);

    // 5) out projection + residual
    dim3 go(CCH / 128, MROWS / 128);
    tgemm_k<<<go, 256, GEMM_SMEM>>>(Ob, ow2, x1, MROWS, CCH, 1024, 2, x, 0, 0);

    // 6) rmsnorm2
    rmsnorm_k<<<MROWS, 256>>>(x1, rms2, mlp);

    // 7) MLP
    dim3 gg(HID / 128, MROWS / 128);
    tgemm_k<<<gg, 256, GEMM_SMEM>>>(mlp, gw2, gate, MROWS, HID, CCH, 0, nullptr, 0, 0);
    tgemm_k<<<gg, 256, GEMM_SMEM>>>(mlp, uw2, hb,   MROWS, HID, CCH, 3, gate,    0, 0);
    dim3 gd(CCH / 128, MROWS / 128);
    tgemm_k<<<gd, 256, GEMM_SMEM>>>(hb, dw2, out, MROWS, CCH, HID, 2, x1, 0, 0);

    // 8) kurtosis
    kurt_rows_k<<<MROWS, 256>>>(out, rowk);
    kurt_final_k<<<1, 256>>>(rowk, ksum, out + (size_t)MROWS * CCH);
}

// round 13
// speedup vs baseline: 1.0385x; 1.0352x over previous
#include <cuda_runtime.h>
#include <math.h>

// ---------------- problem constants ----------------
#define BB   2
#define TT   2048
#define CCH  1024
#define NHQ  16
#define NKV  8
#define HD   64
#define WIN  512
#define HID  4096
#define MROWS (BB*TT)   // 4096

// ---------------- scratch (device globals; no allocs allowed) ----------------
__device__ float g_attn_in[MROWS*CCH];      // 16 MB
__device__ float g_q[BB*NHQ*TT*HD];         // 16 MB  (b,hq,t,d)
__device__ float g_k[BB*NKV*TT*HD];         //  8 MB
__device__ float g_v[BB*NKV*TT*HD];         //  8 MB
__device__ float g_O[MROWS*CCH];            // 16 MB  (b,t,hq,d)
__device__ float g_x1[MROWS*CCH];           // 16 MB
__device__ float g_mlp[MROWS*CCH];          // 16 MB
__device__ float g_h[MROWS*HID];            // 64 MB
__device__ float g_rowk[MROWS];
__device__ float g_rope_s[TT*32];
__device__ float g_rope_c[TT*32];
__device__ float g_wc[15*1024*1024];        // 60 MB: tf32-rounded, [N,K] transposed weights

// weight offsets inside g_wc (floats)
#define OFF_QW 0
#define OFF_KW (OFF_QW + CCH*1024)
#define OFF_VW (OFF_KW + CCH*512)
#define OFF_OW (OFF_VW + CCH*512)
#define OFF_GW (OFF_OW + 1024*CCH)
#define OFF_UW (OFF_GW + CCH*HID)
#define OFF_DW (OFF_UW + CCH*HID)

// ---------------- helpers ----------------
__device__ __forceinline__ float tf32r(float f) {
    unsigned u;
    asm("cvt.rna.tf32.f32 %0, %1;" : "=r"(u) : "f"(f));
    return __uint_as_float(u);
}

__device__ __forceinline__ float blockReduceSum(float v) {
    __shared__ float sh[8];
    int lane = threadIdx.x & 31, wid = threadIdx.x >> 5;
    #pragma unroll
    for (int o = 16; o > 0; o >>= 1) v += __shfl_xor_sync(0xffffffffu, v, o);
    __syncthreads();
    if (lane == 0) sh[wid] = v;
    __syncthreads();
    if (wid == 0) {
        float r = (lane < 8) ? sh[lane] : 0.f;
        #pragma unroll
        for (int o = 4; o > 0; o >>= 1) r += __shfl_xor_sync(0xffffffffu, r, o);
        if (lane == 0) sh[0] = r;
    }
    __syncthreads();
    return sh[0];
}

__device__ __forceinline__ void cpa16(float* dst, const float* src) {
    unsigned d = (unsigned)__cvta_generic_to_shared(dst);
    asm volatile("cp.async.cg.shared.global [%0], [%1], 16;" :: "r"(d), "l"(src));
}

__device__ __forceinline__ void ldsm4(unsigned* r, unsigned saddr) {
    asm volatile("ldmatrix.sync.aligned.m8n8.x4.shared.b16 {%0,%1,%2,%3}, [%4];"
        : "=r"(r[0]), "=r"(r[1]), "=r"(r[2]), "=r"(r[3]) : "r"(saddr));
}

__device__ __forceinline__ void ldsm2(unsigned* r, unsigned saddr) {
    asm volatile("ldmatrix.sync.aligned.m8n8.x2.shared.b16 {%0,%1}, [%2];"
        : "=r"(r[0]), "=r"(r[1]) : "r"(saddr));
}

__device__ __forceinline__ void mma_tf32(float* c, const unsigned* a, const unsigned* b) {
    asm volatile(
        "mma.sync.aligned.m16n8k8.row.col.f32.tf32.tf32.f32 "
        "{%0,%1,%2,%3}, {%4,%5,%6,%7}, {%8,%9}, {%0,%1,%2,%3};"
        : "+f"(c[0]), "+f"(c[1]), "+f"(c[2]), "+f"(c[3])
        : "r"(a[0]), "r"(a[1]), "r"(a[2]), "r"(a[3]), "r"(b[0]), "r"(b[1]));
}

// ---------------- weight prep: transpose [K,N] -> [N,K] + tf32 round ----------------
__global__ __launch_bounds__(256) void wprep_k(const float* __restrict__ in,
                                               float* __restrict__ out, int K, int N) {
    __shared__ float tile[32][33];
    int n0 = blockIdx.x * 32, k0 = blockIdx.y * 32;
    int tx = threadIdx.x, ty = threadIdx.y;   // 32 x 8
    #pragma unroll
    for (int i = 0; i < 32; i += 8)
        tile[ty + i][tx] = in[(size_t)(k0 + ty + i) * N + n0 + tx];
    __syncthreads();
    #pragma unroll
    for (int i = 0; i < 32; i += 8)
        out[(size_t)(n0 + ty + i) * K + k0 + tx] = tf32r(tile[tx][ty + i]);
}

// ---------------- RMSNorm (emits tf32-rounded output) ----------------
__global__ __launch_bounds__(256) void rmsnorm_k(const float* __restrict__ x,
                                                 const float* __restrict__ scale,
                                                 float* __restrict__ out) {
    int row = blockIdx.x;
    const float* xr = x + (size_t)row * CCH;
    float s = 0.f;
    for (int i = threadIdx.x; i < CCH; i += 256) { float v = xr[i]; s += v * v; }
    s = blockReduceSum(s);
    float inv = rsqrtf(s / CCH + 1e-6f);
    float* orow = out + (size_t)row * CCH;
    for (int i = threadIdx.x; i < CCH; i += 256)
        orow[i] = tf32r(xr[i] * inv * (1.f + scale[i]));
}

// ---------------- tf32 GEMM, ldmatrix fragments, cp.async 3-stage ----------------
// A [M,K] row-major, B [N,K] row-major (pre-transposed). CTA 128x128, BK=32,
// 8 warps (2x4), warp tile 64x32, m16n8k8.
// mode 1: head-major scatter (tf32-rounded); mode 2: C = acc + aux
#define TPITCH 36
#define TSZ (128*TPITCH)                 // floats per tile
#define NSTAGE 3
#define GEMM_SMEM (NSTAGE*2*TSZ*4)       // 110592 B
#define GU_SMEM   (NSTAGE*3*TSZ*4)       // 165888 B

__global__ __launch_bounds__(256, 2) void tgemm_k(const float* __restrict__ A,
                                                  const float* __restrict__ B,
                                                  float* __restrict__ C,
                                                  int M, int N, int K,
                                                  int mode, const float* __restrict__ aux,
                                                  int Tdim, int nheads) {
    extern __shared__ float sm[];

    const int tid  = threadIdx.x;
    const int bx   = blockIdx.x, by = blockIdx.y;
    const int warp = tid >> 5, lane = tid & 31;
    const int wm = warp & 1, wn = warp >> 1;     // 2 x 4 warp grid
    const int mw = wm * 64, nw = wn * 32;
    const int grp = lane >> 2, qd = lane & 3;

    const float* Ab = A + (size_t)by * 128 * K;
    const float* Bb = B + (size_t)bx * 128 * K;

    const int lrow = tid >> 3;             // + i*32
    const int lcol = (tid & 7) * 4;

    // ldmatrix per-lane addressing
    const int sub = lane >> 3, rr = lane & 7;
    const int aRowL = mw + ((sub & 1) << 3) + rr;    // + mi*16
    const int aColL = (sub >> 1) << 2;               // + kk
    const int laneB = lane & 15;
    const int bRowL = nw + (laneB & 7);              // + ni*8
    const int bColL = ((laneB >> 3) & 1) << 2;       // + kk

    const unsigned sbase = (unsigned)__cvta_generic_to_shared(sm);

    float acc[4][4][4];
    #pragma unroll
    for (int mi = 0; mi < 4; mi++)
        #pragma unroll
        for (int ni = 0; ni < 4; ni++)
            #pragma unroll
            for (int r = 0; r < 4; r++) acc[mi][ni][r] = 0.f;

    const int nK = K >> 5;

    #define ISSUE(kt, st) do {                                                    \
        float* As_ = sm + (st) * 2 * TSZ;                                         \
        float* Bs_ = As_ + TSZ;                                                   \
        const float* Ag = Ab + (size_t)(kt) * 32;                                 \
        const float* Bg = Bb + (size_t)(kt) * 32;                                 \
        _Pragma("unroll")                                                         \
        for (int i_ = 0; i_ < 4; i_++) {                                          \
            int r_ = lrow + i_ * 32;                                              \
            cpa16(&As_[r_ * TPITCH + lcol], Ag + (size_t)r_ * K + lcol);          \
            cpa16(&Bs_[r_ * TPITCH + lcol], Bg + (size_t)r_ * K + lcol);          \
        }                                                                         \
    } while (0)

    ISSUE(0, 0);
    asm volatile("cp.async.commit_group;");
    ISSUE(1, 1);
    asm volatile("cp.async.commit_group;");

    for (int kt = 0; kt < nK; kt++) {
        asm volatile("cp.async.wait_group 1;");
        __syncthreads();
        const int st = kt % NSTAGE;
        if (kt + 2 < nK) {
            ISSUE(kt + 2, (kt + 2) % NSTAGE);
        }
        asm volatile("cp.async.commit_group;");

        const unsigned aB = sbase + (st * 2 * TSZ) * 4;
        const unsigned bB = aB + TSZ * 4;

        #pragma unroll
        for (int ks = 0; ks < 4; ks++) {
            const int kk = ks * 8;
            unsigned af[4][4], bf[4][2];
            #pragma unroll
            for (int mi = 0; mi < 4; mi++)
                ldsm4(af[mi], aB + (((aRowL + mi * 16) * TPITCH) + kk + aColL) * 4);
            #pragma unroll
            for (int ni = 0; ni < 4; ni++)
                ldsm2(bf[ni], bB + (((bRowL + ni * 8) * TPITCH) + kk + bColL) * 4);
            #pragma unroll
            for (int mi = 0; mi < 4; mi++)
                #pragma unroll
                for (int ni = 0; ni < 4; ni++)
                    mma_tf32(acc[mi][ni], af[mi], bf[ni]);
        }
        __syncthreads();
    }
    #undef ISSUE

    // epilogue
    #pragma unroll
    for (int mi = 0; mi < 4; mi++) {
        #pragma unroll
        for (int ni = 0; ni < 4; ni++) {
            int row0 = by * 128 + mw + mi * 16 + grp;
            int col  = bx * 128 + nw + ni * 8 + qd * 2;
            #pragma unroll
            for (int half = 0; half < 2; half++) {
                int row = row0 + half * 8;
                float v0 = acc[mi][ni][half * 2 + 0];
                float v1 = acc[mi][ni][half * 2 + 1];
                if (mode == 1) {
                    int bi = row / Tdim, s = row % Tdim;
                    int hq = col >> 6, d = col & 63;
                    size_t base = (((size_t)(bi * nheads + hq)) * Tdim + s) * 64 + d;
                    *(float2*)&C[base] = make_float2(tf32r(v0), tf32r(v1));
                } else if (mode == 2) {
                    size_t idx = (size_t)row * N + col;
                    float2 a2 = *(const float2*)&aux[idx];
                    *(float2*)&C[idx] = make_float2(v0 + a2.x, v1 + a2.y);
                } else {
                    *(float2*)&C[(size_t)row * N + col] = make_float2(v0, v1);
                }
            }
        }
    }
}

// ---------------- fused gate+up GEMM: h = up * silu(gate) ----------------
// A [M,K], Bg/Bu [N,K]. Same tiling; two accumulator sets; writes h (tf32-rounded).
__global__ __launch_bounds__(256, 1) void tgemm_gu_k(const float* __restrict__ A,
                                                     const float* __restrict__ Bg,
                                                     const float* __restrict__ Bu,
                                                     float* __restrict__ H,
                                                     int M, int N, int K) {
    extern __shared__ float sm[];

    const int tid  = threadIdx.x;
    const int bx   = blockIdx.x, by = blockIdx.y;
    const int warp = tid >> 5, lane = tid & 31;
    const int wm = warp & 1, wn = warp >> 1;
    const int mw = wm * 64, nw = wn * 32;
    const int grp = lane >> 2, qd = lane & 3;

    const float* Ab  = A  + (size_t)by * 128 * K;
    const float* Bgb = Bg + (size_t)bx * 128 * K;
    const float* Bub = Bu + (size_t)bx * 128 * K;

    const int lrow = tid >> 3;
    const int lcol = (tid & 7) * 4;

    const int sub = lane >> 3, rr = lane & 7;
    const int aRowL = mw + ((sub & 1) << 3) + rr;
    const int aColL = (sub >> 1) << 2;
    const int laneB = lane & 15;
    const int bRowL = nw + (laneB & 7);
    const int bColL = ((laneB >> 3) & 1) << 2;

    const unsigned sbase = (unsigned)__cvta_generic_to_shared(sm);

    float accg[4][4][4], accu[4][4][4];
    #pragma unroll
    for (int mi = 0; mi < 4; mi++)
        #pragma unroll
        for (int ni = 0; ni < 4; ni++)
            #pragma unroll
            for (int r = 0; r < 4; r++) { accg[mi][ni][r] = 0.f; accu[mi][ni][r] = 0.f; }

    const int nK = K >> 5;

    #define ISSUE_GU(kt, st) do {                                                 \
        float* As_ = sm + (st) * 3 * TSZ;                                         \
        float* Bg_ = As_ + TSZ;                                                   \
        float* Bu_ = As_ + 2 * TSZ;                                               \
        const float* Ag  = Ab  + (size_t)(kt) * 32;                               \
        const float* Bgg = Bgb + (size_t)(kt) * 32;                               \
        const float* Bug = Bub + (size_t)(kt) * 32;                               \
        _Pragma("unroll")                                                         \
        for (int i_ = 0; i_ < 4; i_++) {                                          \
            int r_ = lrow + i_ * 32;                                              \
            cpa16(&As_[r_ * TPITCH + lcol], Ag  + (size_t)r_ * K + lcol);         \
            cpa16(&Bg_[r_ * TPITCH + lcol], Bgg + (size_t)r_ * K + lcol);         \
            cpa16(&Bu_[r_ * TPITCH + lcol], Bug + (size_t)r_ * K + lcol);         \
        }                                                                         \
    } while (0)

    ISSUE_GU(0, 0);
    asm volatile("cp.async.commit_group;");
    ISSUE_GU(1, 1);
    asm volatile("cp.async.commit_group;");

    for (int kt = 0; kt < nK; kt++) {
        asm volatile("cp.async.wait_group 1;");
        __syncthreads();
        const int st = kt % NSTAGE;
        if (kt + 2 < nK) {
            ISSUE_GU(kt + 2, (kt + 2) % NSTAGE);
        }
        asm volatile("cp.async.commit_group;");

        const unsigned aB = sbase + (st * 3 * TSZ) * 4;
        const unsigned gB = aB + TSZ * 4;
        const unsigned uB = aB + 2 * TSZ * 4;

        #pragma unroll
        for (int ks = 0; ks < 4; ks++) {
            const int kk = ks * 8;
            unsigned af[4][4], bfg[4][2], bfu[4][2];
            #pragma unroll
            for (int mi = 0; mi < 4; mi++)
                ldsm4(af[mi], aB + (((aRowL + mi * 16) * TPITCH) + kk + aColL) * 4);
            #pragma unroll
            for (int ni = 0; ni < 4; ni++) {
                unsigned off = (((bRowL + ni * 8) * TPITCH) + kk + bColL) * 4;
                ldsm2(bfg[ni], gB + off);
                ldsm2(bfu[ni], uB + off);
            }
            #pragma unroll
            for (int mi = 0; mi < 4; mi++)
                #pragma unroll
                for (int ni = 0; ni < 4; ni++) {
                    mma_tf32(accg[mi][ni], af[mi], bfg[ni]);
                    mma_tf32(accu[mi][ni], af[mi], bfu[ni]);
                }
        }
        __syncthreads();
    }
    #undef ISSUE_GU

    #pragma unroll
    for (int mi = 0; mi < 4; mi++) {
        #pragma unroll
        for (int ni = 0; ni < 4; ni++) {
            int row0 = by * 128 + mw + mi * 16 + grp;
            int col  = bx * 128 + nw + ni * 8 + qd * 2;
            #pragma unroll
            for (int half = 0; half < 2; half++) {
                int row = row0 + half * 8;
                float g0 = accg[mi][ni][half * 2 + 0], u0 = accu[mi][ni][half * 2 + 0];
                float g1 = accg[mi][ni][half * 2 + 1], u1 = accu[mi][ni][half * 2 + 1];
                float s0 = g0 / (1.f + __expf(-g0));
                float s1 = g1 / (1.f + __expf(-g1));
                size_t idx = (size_t)row * N + col;
                *(float2*)&H[idx] = make_float2(tf32r(u0 * s0), tf32r(u1 * s1));
            }
        }
    }
}

// ---------------- RoPE table + apply (rounded output) ----------------
__global__ void rope_table_k() {
    int idx = blockIdx.x * 256 + threadIdx.x;   // TT*32 = 65536
    int i = idx & 31, t = idx >> 5;
    double freq = exp(-(double)i / 32.0 * 13.815510557964274);  // ln(1e6)
    double ang = (double)t * freq;
    g_rope_s[idx] = (float)sin(ang);
    g_rope_c[idx] = (float)cos(ang);
}

__global__ void rope_k(float* __restrict__ buf, int total /* BH*T*32 */) {
    int idx = blockIdx.x * blockDim.x + threadIdx.x;
    if (idx >= total) return;
    int i  = idx & 31;
    int t  = (idx >> 5) & (TT - 1);
    int bh = idx >> 16;
    int ti = (idx & 0xFFFF);
    float sn = g_rope_s[ti], cs = g_rope_c[ti];
    float* p = buf + ((size_t)bh * TT + t) * 64;
    float x1 = p[i], x2 = p[i + 32];
    p[i]      = tf32r(x1 * cs - x2 * sn);
    p[i + 32] = tf32r(x2 * cs + x1 * sn);
}

// ---------------- sliding-window flash attention ----------------
#define PITCH 65
__global__ __launch_bounds__(256) void attn_k(const float* __restrict__ q,
                                              const float* __restrict__ k,
                                              const float* __restrict__ v,
                                              float* __restrict__ O) {
    extern __shared__ float sma[];
    float* Qs = sma;                      // 64*65
    float* Ks = Qs + 64 * PITCH;
    float* Vs = Ks + 64 * PITCH;
    float* Ss = Vs + 64 * PITCH;
    float* m_s  = Ss + 64 * PITCH;
    float* l_s  = m_s + 64;
    float* al_s = l_s + 64;

    const int qt = blockIdx.x, hq = blockIdx.y, b = blockIdx.z;
    const int hk = hq & (NKV - 1);
    const int tid = threadIdx.x;
    const int q0 = qt * 64;
    const float* qb = q + (((size_t)(b * NHQ + hq)) * TT + q0) * 64;
    const float* kb = k + ((size_t)(b * NKV + hk)) * TT * 64;
    const float* vb = v + ((size_t)(b * NKV + hk)) * TT * 64;

    {
        int r = tid >> 2, cg = (tid & 3) * 16;
        #pragma unroll
        for (int g = 0; g < 16; g += 4) {
            float4 t4 = *(const float4*)(qb + (size_t)r * 64 + cg + g);
            Qs[r * PITCH + cg + g + 0] = t4.x; Qs[r * PITCH + cg + g + 1] = t4.y;
            Qs[r * PITCH + cg + g + 2] = t4.z; Qs[r * PITCH + cg + g + 3] = t4.w;
        }
    }
    if (tid < 64) { m_s[tid] = -1e30f; l_s[tid] = 0.f; }

    const int tr = tid >> 4, tc = tid & 15;
    const int r0 = tr * 4, c0 = tc * 4;
    float o[4][4];
    #pragma unroll
    for (int i = 0; i < 4; i++)
        #pragma unroll
        for (int j = 0; j < 4; j++) o[i][j] = 0.f;

    int kb_lo = max(0, q0 - (WIN - 1)) >> 6;
    for (int kbi = kb_lo; kbi <= qt; kbi++) {
        int j0 = kbi * 64;
        __syncthreads();
        {
            int r = tid >> 2, cg = (tid & 3) * 16;
            #pragma unroll
            for (int g = 0; g < 16; g += 4) {
                float4 t4 = *(const float4*)(kb + ((size_t)(j0 + r)) * 64 + cg + g);
                Ks[r * PITCH + cg + g + 0] = t4.x; Ks[r * PITCH + cg + g + 1] = t4.y;
                Ks[r * PITCH + cg + g + 2] = t4.z; Ks[r * PITCH + cg + g + 3] = t4.w;
                float4 u4 = *(const float4*)(vb + ((size_t)(j0 + r)) * 64 + cg + g);
                Vs[r * PITCH + cg + g + 0] = u4.x; Vs[r * PITCH + cg + g + 1] = u4.y;
                Vs[r * PITCH + cg + g + 2] = u4.z; Vs[r * PITCH + cg + g + 3] = u4.w;
            }
        }
        __syncthreads();

        float sreg[4][4];
        #pragma unroll
        for (int i = 0; i < 4; i++)
            #pragma unroll
            for (int j = 0; j < 4; j++) sreg[i][j] = 0.f;
        #pragma unroll 8
        for (int kk = 0; kk < 64; kk++) {
            float qv[4], kv[4];
            #pragma unroll
            for (int i = 0; i < 4; i++) qv[i] = Qs[(r0 + i) * PITCH + kk];
            #pragma unroll
            for (int j = 0; j < 4; j++) kv[j] = Ks[(c0 + j) * PITCH + kk];
            #pragma unroll
            for (int i = 0; i < 4; i++)
                #pragma unroll
                for (int j = 0; j < 4; j++) sreg[i][j] += qv[i] * kv[j];
        }
        #pragma unroll
        for (int i = 0; i < 4; i++) {
            int sa = q0 + r0 + i;
            #pragma unroll
            for (int j = 0; j < 4; j++) {
                int ja = j0 + c0 + j;
                float val = sreg[i][j] * 0.125f * 0.02f;
                float th;
                asm("tanh.approx.f32 %0, %1;" : "=f"(th) : "f"(val));
                val = 50.f * th;
                bool valid = (ja <= sa) && (sa - ja < WIN);
                Ss[(r0 + i) * PITCH + (c0 + j)] = valid ? val : -1e30f;
            }
        }
        __syncthreads();

        if (tid < 64) {
            float mold = m_s[tid];
            float mx = mold;
            float* srow = Ss + tid * PITCH;
            #pragma unroll 8
            for (int c2 = 0; c2 < 64; c2++) mx = fmaxf(mx, srow[c2]);
            if (mx < -1e29f) {
                al_s[tid] = 1.f;
                #pragma unroll 8
                for (int c2 = 0; c2 < 64; c2++) srow[c2] = 0.f;
            } else {
                float al = __expf(mold - mx);
                float ls = 0.f;
                #pragma unroll 8
                for (int c2 = 0; c2 < 64; c2++) {
                    float p = __expf(srow[c2] - mx);
                    srow[c2] = p; ls += p;
                }
                l_s[tid] = l_s[tid] * al + ls;
                m_s[tid] = mx;
                al_s[tid] = al;
            }
        }
        __syncthreads();

        #pragma unroll
        for (int i = 0; i < 4; i++) {
            float al = al_s[r0 + i];
            #pragma unroll
            for (int j = 0; j < 4; j++) o[i][j] *= al;
        }
        #pragma unroll 8
        for (int kk = 0; kk < 64; kk++) {
            float vv0 = Vs[kk * PITCH + c0 + 0];
            float vv1 = Vs[kk * PITCH + c0 + 1];
            float vv2 = Vs[kk * PITCH + c0 + 2];
            float vv3 = Vs[kk * PITCH + c0 + 3];
            #pragma unroll
            for (int i = 0; i < 4; i++) {
                float p = Ss[(r0 + i) * PITCH + kk];
                o[i][0] += p * vv0; o[i][1] += p * vv1;
                o[i][2] += p * vv2; o[i][3] += p * vv3;
            }
        }
    }

    #pragma unroll
    for (int i = 0; i < 4; i++) {
        float invl = 1.f / l_s[r0 + i];
        size_t base = ((size_t)(b * TT + q0 + r0 + i)) * CCH + hq * 64 + c0;
        #pragma unroll
        for (int j = 0; j < 4; j++) O[base + j] = tf32r(o[i][j] * invl);
    }
}

// ---------------- excess kurtosis ----------------
__global__ __launch_bounds__(256) void kurt_rows_k(const float* __restrict__ x,
                                                   float* __restrict__ rowk) {
    int row = blockIdx.x;
    const float* xr = x + (size_t)row * CCH;
    float s = 0.f;
    for (int i = threadIdx.x; i < CCH; i += 256) s += xr[i];
    s = blockReduceSum(s);
    float mean = s / CCH;
    float a2 = 0.f, a4 = 0.f;
    for (int i = threadIdx.x; i < CCH; i += 256) {
        float d = xr[i] - mean; float d2 = d * d;
        a2 += d2; a4 += d2 * d2;
    }
    a2 = blockReduceSum(a2);
    a4 = blockReduceSum(a4);
    if (threadIdx.x == 0) {
        float var = a2 / CCH, m4 = a4 / CCH;
        float kurt = m4 / (var * var + 1e-6f) - 3.f;
        rowk[row] = fmaxf(kurt, 0.f);
    }
}

__global__ __launch_bounds__(256) void kurt_final_k(const float* __restrict__ rowk,
                                                    const float* __restrict__ ksum,
                                                    float* __restrict__ outp) {
    float s = 0.f;
    for (int i = threadIdx.x; i < MROWS; i += 256) s += rowk[i];
    s = blockReduceSum(s);
    if (threadIdx.x == 0) outp[0] = s + ksum[0];
}

// ---------------- launcher ----------------
extern "C" void kernel_launch(void* const* d_in, const int* in_sizes, int n_in,
                              void* d_out, int out_size) {
    (void)in_sizes; (void)n_in; (void)out_size;
    const float* x    = (const float*)d_in[0];
    const float* ksum = (const float*)d_in[1];
    const float* rms1 = (const float*)d_in[2];
    const float* qw   = (const float*)d_in[3];
    const float* kw   = (const float*)d_in[4];
    const float* vw   = (const float*)d_in[5];
    const float* ow   = (const float*)d_in[6];
    const float* rms2 = (const float*)d_in[7];
    const float* gw   = (const float*)d_in[8];
    const float* uw   = (const float*)d_in[9];
    const float* dw   = (const float*)d_in[10];
    float* out = (float*)d_out;

    float *attn_in, *qb, *kb, *vb, *Ob, *x1, *mlp, *hb, *rowk, *wc;
    cudaGetSymbolAddress((void**)&attn_in, g_attn_in);
    cudaGetSymbolAddress((void**)&qb,   g_q);
    cudaGetSymbolAddress((void**)&kb,   g_k);
    cudaGetSymbolAddress((void**)&vb,   g_v);
    cudaGetSymbolAddress((void**)&Ob,   g_O);
    cudaGetSymbolAddress((void**)&x1,   g_x1);
    cudaGetSymbolAddress((void**)&mlp,  g_mlp);
    cudaGetSymbolAddress((void**)&hb,   g_h);
    cudaGetSymbolAddress((void**)&rowk, g_rowk);
    cudaGetSymbolAddress((void**)&wc,   g_wc);

    float* qw2 = wc + OFF_QW;  float* kw2 = wc + OFF_KW;
    float* vw2 = wc + OFF_VW;  float* ow2 = wc + OFF_OW;
    float* gw2 = wc + OFF_GW;  float* uw2 = wc + OFF_UW;
    float* dw2 = wc + OFF_DW;

    cudaFuncSetAttribute(tgemm_k,    cudaFuncAttributeMaxDynamicSharedMemorySize, GEMM_SMEM);
    cudaFuncSetAttribute(tgemm_gu_k, cudaFuncAttributeMaxDynamicSharedMemorySize, GU_SMEM);

    // 0) weight prep (transpose [K,N]->[N,K] + tf32 round) + rope table
    dim3 tb(32, 8);
    wprep_k<<<dim3(1024/32, 1024/32), tb>>>(qw, qw2, 1024, 1024);
    wprep_k<<<dim3(512/32,  1024/32), tb>>>(kw, kw2, 1024, 512);
    wprep_k<<<dim3(512/32,  1024/32), tb>>>(vw, vw2, 1024, 512);
    wprep_k<<<dim3(1024/32, 1024/32), tb>>>(ow, ow2, 1024, 1024);
    wprep_k<<<dim3(HID/32,  1024/32), tb>>>(gw, gw2, 1024, HID);
    wprep_k<<<dim3(HID/32,  1024/32), tb>>>(uw, uw2, 1024, HID);
    wprep_k<<<dim3(1024/32, HID/32),  tb>>>(dw, dw2, HID, 1024);
    rope_table_k<<<(TT * 32) / 256, 256>>>();

    // 1) rmsnorm1 (tf32-rounded out)
    rmsnorm_k<<<MROWS, 256>>>(x, rms1, attn_in);

    // 2) QKV projections
    dim3 gq(1024 / 128, MROWS / 128);
    tgemm_k<<<gq, 256, GEMM_SMEM>>>(attn_in, qw2, qb, MROWS, 1024, CCH, 1, nullptr, TT, NHQ);
    dim3 gkv(512 / 128, MROWS / 128);
    tgemm_k<<<gkv, 256, GEMM_SMEM>>>(attn_in, kw2, kb, MROWS, 512, CCH, 1, nullptr, TT, NKV);
    tgemm_k<<<gkv, 256, GEMM_SMEM>>>(attn_in, vw2, vb, MROWS, 512, CCH, 1, nullptr, TT, NKV);

    // 3) RoPE
    int nq = BB * NHQ * TT * 32;
    rope_k<<<nq / 256, 256>>>(qb, nq);
    int nk = BB * NKV * TT * 32;
    rope_k<<<nk / 256, 256>>>(kb, nk);

    // 4) attention
    int smemAttn = (4 * 64 * PITCH + 3 * 64) * (int)sizeof(float);
    cudaFuncSetAttribute(attn_k, cudaFuncAttributeMaxDynamicSharedMemorySize, smemAttn);
    dim3 ga(TT / 64, NHQ, BB);
    attn_k<<<ga, 256, smemAttn>>>(qb, kb, vb, Ob);

    // 5) out projection + residual
    dim3 go(CCH / 128, MROWS / 128);
    tgemm_k<<<go, 256, GEMM_SMEM>>>(Ob, ow2, x1, MROWS, CCH, 1024, 2, x, 0, 0);

    // 6) rmsnorm2
    rmsnorm_k<<<MROWS, 256>>>(x1, rms2, mlp);

    // 7) MLP: fused gate+up, then down + residual (writes straight to d_out)
    dim3 gg(HID / 128, MROWS / 128);
    tgemm_gu_k<<<gg, 256, GU_SMEM>>>(mlp, gw2, uw2, hb, MROWS, HID, CCH);
    dim3 gd(CCH / 128, MROWS / 128);
    tgemm_k<<<gd, 256, GEMM_SMEM>>>(hb, dw2, out, MROWS, CCH, HID, 2, x1, 0, 0);

    // 8) kurtosis
    kurt_rows_k<<<MROWS, 256>>>(out, rowk);
    kurt_final_k<<<1, 256>>>(rowk, ksum, out + (size_t)MROWS * CCH);
}

// round 14
// speedup vs baseline: 1.0404x; 1.0019x over previous
#include <cuda_runtime.h>
#include <math.h>

// ---------------- problem constants ----------------
#define BB   2
#define TT   2048
#define CCH  1024
#define NHQ  16
#define NKV  8
#define HD   64
#define WIN  512
#define HID  4096
#define MROWS (BB*TT)   // 4096

// ---------------- scratch (device globals; no allocs allowed) ----------------
__device__ float g_attn_in[MROWS*CCH];      // 16 MB
__device__ float g_q[BB*NHQ*TT*HD];         // 16 MB  (b,hq,t,d)
__device__ float g_k[BB*NKV*TT*HD];         //  8 MB
__device__ float g_v[BB*NKV*TT*HD];         //  8 MB
__device__ float g_O[MROWS*CCH];            // 16 MB  (b,t,hq,d)
__device__ float g_x1[MROWS*CCH];           // 16 MB
__device__ float g_mlp[MROWS*CCH];          // 16 MB
__device__ float g_h[MROWS*HID];            // 64 MB
__device__ float g_rowk[MROWS];
__device__ float g_rope_s[TT*32];
__device__ float g_rope_c[TT*32];
__device__ float g_wc[15*1024*1024];        // 60 MB: tf32-rounded, [N,K] transposed weights

// weight offsets inside g_wc (floats)
#define OFF_QW 0
#define OFF_KW (OFF_QW + CCH*1024)
#define OFF_VW (OFF_KW + CCH*512)
#define OFF_OW (OFF_VW + CCH*512)
#define OFF_GW (OFF_OW + 1024*CCH)
#define OFF_UW (OFF_GW + CCH*HID)
#define OFF_DW (OFF_UW + CCH*HID)

// ---------------- helpers ----------------
__device__ __forceinline__ float tf32r(float f) {
    unsigned u;
    asm("cvt.rna.tf32.f32 %0, %1;" : "=r"(u) : "f"(f));
    return __uint_as_float(u);
}

__device__ __forceinline__ float blockReduceSum(float v) {
    __shared__ float sh[8];
    int lane = threadIdx.x & 31, wid = threadIdx.x >> 5;
    #pragma unroll
    for (int o = 16; o > 0; o >>= 1) v += __shfl_xor_sync(0xffffffffu, v, o);
    __syncthreads();
    if (lane == 0) sh[wid] = v;
    __syncthreads();
    if (wid == 0) {
        float r = (lane < 8) ? sh[lane] : 0.f;
        #pragma unroll
        for (int o = 4; o > 0; o >>= 1) r += __shfl_xor_sync(0xffffffffu, r, o);
        if (lane == 0) sh[0] = r;
    }
    __syncthreads();
    return sh[0];
}

__device__ __forceinline__ void cpa16(float* dst, const float* src) {
    unsigned d = (unsigned)__cvta_generic_to_shared(dst);
    asm volatile("cp.async.cg.shared.global [%0], [%1], 16;" :: "r"(d), "l"(src));
}

__device__ __forceinline__ void ldsm4(unsigned* r, unsigned saddr) {
    asm volatile("ldmatrix.sync.aligned.m8n8.x4.shared.b16 {%0,%1,%2,%3}, [%4];"
        : "=r"(r[0]), "=r"(r[1]), "=r"(r[2]), "=r"(r[3]) : "r"(saddr));
}

__device__ __forceinline__ void ldsm2(unsigned* r, unsigned saddr) {
    asm volatile("ldmatrix.sync.aligned.m8n8.x2.shared.b16 {%0,%1}, [%2];"
        : "=r"(r[0]), "=r"(r[1]) : "r"(saddr));
}

__device__ __forceinline__ void mma_tf32(float* c, const unsigned* a, const unsigned* b) {
    asm volatile(
        "mma.sync.aligned.m16n8k8.row.col.f32.tf32.tf32.f32 "
        "{%0,%1,%2,%3}, {%4,%5,%6,%7}, {%8,%9}, {%0,%1,%2,%3};"
        : "+f"(c[0]), "+f"(c[1]), "+f"(c[2]), "+f"(c[3])
        : "r"(a[0]), "r"(a[1]), "r"(a[2]), "r"(a[3]), "r"(b[0]), "r"(b[1]));
}

// ---------------- weight prep: transpose [K,N] -> [N,K] + tf32 round ----------------
__global__ __launch_bounds__(256) void wprep_k(const float* __restrict__ in,
                                               float* __restrict__ out, int K, int N) {
    __shared__ float tile[32][33];
    int n0 = blockIdx.x * 32, k0 = blockIdx.y * 32;
    int tx = threadIdx.x, ty = threadIdx.y;   // 32 x 8
    #pragma unroll
    for (int i = 0; i < 32; i += 8)
        tile[ty + i][tx] = in[(size_t)(k0 + ty + i) * N + n0 + tx];
    __syncthreads();
    #pragma unroll
    for (int i = 0; i < 32; i += 8)
        out[(size_t)(n0 + ty + i) * K + k0 + tx] = tf32r(tile[tx][ty + i]);
}

// ---------------- RMSNorm (emits tf32-rounded output) ----------------
__global__ __launch_bounds__(256) void rmsnorm_k(const float* __restrict__ x,
                                                 const float* __restrict__ scale,
                                                 float* __restrict__ out) {
    int row = blockIdx.x;
    const float* xr = x + (size_t)row * CCH;
    float s = 0.f;
    for (int i = threadIdx.x; i < CCH; i += 256) { float v = xr[i]; s += v * v; }
    s = blockReduceSum(s);
    float inv = rsqrtf(s / CCH + 1e-6f);
    float* orow = out + (size_t)row * CCH;
    for (int i = threadIdx.x; i < CCH; i += 256)
        orow[i] = tf32r(xr[i] * inv * (1.f + scale[i]));
}

// ---------------- tf32 GEMM, ldmatrix fragments, cp.async 3-stage ----------------
// A [M,K] row-major, B [N,K] row-major (pre-transposed). CTA 128x128, BK=32,
// 8 warps (2x4), warp tile 64x32, m16n8k8.
// mode 1: head-major scatter (tf32-rounded); mode 2: C = acc + aux
#define TPITCH 36
#define TSZ (128*TPITCH)                 // floats per tile
#define NSTAGE 3
#define GEMM_SMEM (NSTAGE*2*TSZ*4)       // 110592 B
#define GU_SMEM   (NSTAGE*3*TSZ*4)       // 165888 B

__global__ __launch_bounds__(256, 2) void tgemm_k(const float* __restrict__ A,
                                                  const float* __restrict__ B,
                                                  float* __restrict__ C,
                                                  int M, int N, int K,
                                                  int mode, const float* __restrict__ aux,
                                                  int Tdim, int nheads) {
    extern __shared__ float sm[];

    const int tid  = threadIdx.x;
    const int bx   = blockIdx.x, by = blockIdx.y;
    const int warp = tid >> 5, lane = tid & 31;
    const int wm = warp & 1, wn = warp >> 1;     // 2 x 4 warp grid
    const int mw = wm * 64, nw = wn * 32;
    const int grp = lane >> 2, qd = lane & 3;

    const float* Ab = A + (size_t)by * 128 * K;
    const float* Bb = B + (size_t)bx * 128 * K;

    const int lrow = tid >> 3;             // + i*32
    const int lcol = (tid & 7) * 4;

    // ldmatrix per-lane addressing
    const int sub = lane >> 3, rr = lane & 7;
    const int aRowL = mw + ((sub & 1) << 3) + rr;    // + mi*16
    const int aColL = (sub >> 1) << 2;               // + kk
    const int laneB = lane & 15;
    const int bRowL = nw + (laneB & 7);              // + ni*8
    const int bColL = ((laneB >> 3) & 1) << 2;       // + kk

    const unsigned sbase = (unsigned)__cvta_generic_to_shared(sm);

    float acc[4][4][4];
    #pragma unroll
    for (int mi = 0; mi < 4; mi++)
        #pragma unroll
        for (int ni = 0; ni < 4; ni++)
            #pragma unroll
            for (int r = 0; r < 4; r++) acc[mi][ni][r] = 0.f;

    const int nK = K >> 5;

    #define ISSUE(kt, st) do {                                                    \
        float* As_ = sm + (st) * 2 * TSZ;                                         \
        float* Bs_ = As_ + TSZ;                                                   \
        const float* Ag = Ab + (size_t)(kt) * 32;                                 \
        const float* Bg = Bb + (size_t)(kt) * 32;                                 \
        _Pragma("unroll")                                                         \
        for (int i_ = 0; i_ < 4; i_++) {                                          \
            int r_ = lrow + i_ * 32;                                              \
            cpa16(&As_[r_ * TPITCH + lcol], Ag + (size_t)r_ * K + lcol);          \
            cpa16(&Bs_[r_ * TPITCH + lcol], Bg + (size_t)r_ * K + lcol);          \
        }                                                                         \
    } while (0)

    ISSUE(0, 0);
    asm volatile("cp.async.commit_group;");
    ISSUE(1, 1);
    asm volatile("cp.async.commit_group;");

    for (int kt = 0; kt < nK; kt++) {
        asm volatile("cp.async.wait_group 1;");
        __syncthreads();
        const int st = kt % NSTAGE;
        if (kt + 2 < nK) {
            ISSUE(kt + 2, (kt + 2) % NSTAGE);
        }
        asm volatile("cp.async.commit_group;");

        const unsigned aB = sbase + (st * 2 * TSZ) * 4;
        const unsigned bB = aB + TSZ * 4;

        #pragma unroll
        for (int ks = 0; ks < 4; ks++) {
            const int kk = ks * 8;
            unsigned af[4][4], bf[4][2];
            #pragma unroll
            for (int mi = 0; mi < 4; mi++)
                ldsm4(af[mi], aB + (((aRowL + mi * 16) * TPITCH) + kk + aColL) * 4);
            #pragma unroll
            for (int ni = 0; ni < 4; ni++)
                ldsm2(bf[ni], bB + (((bRowL + ni * 8) * TPITCH) + kk + bColL) * 4);
            #pragma unroll
            for (int mi = 0; mi < 4; mi++)
                #pragma unroll
                for (int ni = 0; ni < 4; ni++)
                    mma_tf32(acc[mi][ni], af[mi], bf[ni]);
        }
        __syncthreads();
    }
    #undef ISSUE

    // epilogue
    #pragma unroll
    for (int mi = 0; mi < 4; mi++) {
        #pragma unroll
        for (int ni = 0; ni < 4; ni++) {
            int row0 = by * 128 + mw + mi * 16 + grp;
            int col  = bx * 128 + nw + ni * 8 + qd * 2;
            #pragma unroll
            for (int half = 0; half < 2; half++) {
                int row = row0 + half * 8;
                float v0 = acc[mi][ni][half * 2 + 0];
                float v1 = acc[mi][ni][half * 2 + 1];
                if (mode == 1) {
                    int bi = row / Tdim, s = row % Tdim;
                    int hq = col >> 6, d = col & 63;
                    size_t base = (((size_t)(bi * nheads + hq)) * Tdim + s) * 64 + d;
                    *(float2*)&C[base] = make_float2(tf32r(v0), tf32r(v1));
                } else if (mode == 2) {
                    size_t idx = (size_t)row * N + col;
                    float2 a2 = *(const float2*)&aux[idx];
                    *(float2*)&C[idx] = make_float2(v0 + a2.x, v1 + a2.y);
                } else {
                    *(float2*)&C[(size_t)row * N + col] = make_float2(v0, v1);
                }
            }
        }
    }
}

// ---------------- fused gate+up GEMM: h = up * silu(gate) ----------------
// A [M,K], Bg/Bu [N,K]. Same tiling; two accumulator sets; writes h (tf32-rounded).
__global__ __launch_bounds__(256, 1) void tgemm_gu_k(const float* __restrict__ A,
                                                     const float* __restrict__ Bg,
                                                     const float* __restrict__ Bu,
                                                     float* __restrict__ H,
                                                     int M, int N, int K) {
    extern __shared__ float sm[];

    const int tid  = threadIdx.x;
    const int bx   = blockIdx.x, by = blockIdx.y;
    const int warp = tid >> 5, lane = tid & 31;
    const int wm = warp & 1, wn = warp >> 1;
    const int mw = wm * 64, nw = wn * 32;
    const int grp = lane >> 2, qd = lane & 3;

    const float* Ab  = A  + (size_t)by * 128 * K;
    const float* Bgb = Bg + (size_t)bx * 128 * K;
    const float* Bub = Bu + (size_t)bx * 128 * K;

    const int lrow = tid >> 3;
    const int lcol = (tid & 7) * 4;

    const int sub = lane >> 3, rr = lane & 7;
    const int aRowL = mw + ((sub & 1) << 3) + rr;
    const int aColL = (sub >> 1) << 2;
    const int laneB = lane & 15;
    const int bRowL = nw + (laneB & 7);
    const int bColL = ((laneB >> 3) & 1) << 2;

    const unsigned sbase = (unsigned)__cvta_generic_to_shared(sm);

    float accg[4][4][4], accu[4][4][4];
    #pragma unroll
    for (int mi = 0; mi < 4; mi++)
        #pragma unroll
        for (int ni = 0; ni < 4; ni++)
            #pragma unroll
            for (int r = 0; r < 4; r++) { accg[mi][ni][r] = 0.f; accu[mi][ni][r] = 0.f; }

    const int nK = K >> 5;

    #define ISSUE_GU(kt, st) do {                                                 \
        float* As_ = sm + (st) * 3 * TSZ;                                         \
        float* Bg_ = As_ + TSZ;                                                   \
        float* Bu_ = As_ + 2 * TSZ;                                               \
        const float* Ag  = Ab  + (size_t)(kt) * 32;                               \
        const float* Bgg = Bgb + (size_t)(kt) * 32;                               \
        const float* Bug = Bub + (size_t)(kt) * 32;                               \
        _Pragma("unroll")                                                         \
        for (int i_ = 0; i_ < 4; i_++) {                                          \
            int r_ = lrow + i_ * 32;                                              \
            cpa16(&As_[r_ * TPITCH + lcol], Ag  + (size_t)r_ * K + lcol);         \
            cpa16(&Bg_[r_ * TPITCH + lcol], Bgg + (size_t)r_ * K + lcol);         \
            cpa16(&Bu_[r_ * TPITCH + lcol], Bug + (size_t)r_ * K + lcol);         \
        }                                                                         \
    } while (0)

    ISSUE_GU(0, 0);
    asm volatile("cp.async.commit_group;");
    ISSUE_GU(1, 1);
    asm volatile("cp.async.commit_group;");

    for (int kt = 0; kt < nK; kt++) {
        asm volatile("cp.async.wait_group 1;");
        __syncthreads();
        const int st = kt % NSTAGE;
        if (kt + 2 < nK) {
            ISSUE_GU(kt + 2, (kt + 2) % NSTAGE);
        }
        asm volatile("cp.async.commit_group;");

        const unsigned aB = sbase + (st * 3 * TSZ) * 4;
        const unsigned gB = aB + TSZ * 4;
        const unsigned uB = aB + 2 * TSZ * 4;

        #pragma unroll
        for (int ks = 0; ks < 4; ks++) {
            const int kk = ks * 8;
            unsigned af[4][4], bfg[4][2], bfu[4][2];
            #pragma unroll
            for (int mi = 0; mi < 4; mi++)
                ldsm4(af[mi], aB + (((aRowL + mi * 16) * TPITCH) + kk + aColL) * 4);
            #pragma unroll
            for (int ni = 0; ni < 4; ni++) {
                unsigned off = (((bRowL + ni * 8) * TPITCH) + kk + bColL) * 4;
                ldsm2(bfg[ni], gB + off);
                ldsm2(bfu[ni], uB + off);
            }
            #pragma unroll
            for (int mi = 0; mi < 4; mi++)
                #pragma unroll
                for (int ni = 0; ni < 4; ni++) {
                    mma_tf32(accg[mi][ni], af[mi], bfg[ni]);
                    mma_tf32(accu[mi][ni], af[mi], bfu[ni]);
                }
        }
        __syncthreads();
    }
    #undef ISSUE_GU

    #pragma unroll
    for (int mi = 0; mi < 4; mi++) {
        #pragma unroll
        for (int ni = 0; ni < 4; ni++) {
            int row0 = by * 128 + mw + mi * 16 + grp;
            int col  = bx * 128 + nw + ni * 8 + qd * 2;
            #pragma unroll
            for (int half = 0; half < 2; half++) {
                int row = row0 + half * 8;
                float g0 = accg[mi][ni][half * 2 + 0], u0 = accu[mi][ni][half * 2 + 0];
                float g1 = accg[mi][ni][half * 2 + 1], u1 = accu[mi][ni][half * 2 + 1];
                float s0 = g0 / (1.f + __expf(-g0));
                float s1 = g1 / (1.f + __expf(-g1));
                size_t idx = (size_t)row * N + col;
                *(float2*)&H[idx] = make_float2(tf32r(u0 * s0), tf32r(u1 * s1));
            }
        }
    }
}

// ---------------- RoPE table + apply (rounded output) ----------------
__global__ void rope_table_k() {
    int idx = blockIdx.x * 256 + threadIdx.x;   // TT*32 = 65536
    int i = idx & 31, t = idx >> 5;
    double freq = exp(-(double)i / 32.0 * 13.815510557964274);  // ln(1e6)
    double ang = (double)t * freq;
    g_rope_s[idx] = (float)sin(ang);
    g_rope_c[idx] = (float)cos(ang);
}

__global__ void rope_k(float* __restrict__ buf, int total /* BH*T*32 */) {
    int idx = blockIdx.x * blockDim.x + threadIdx.x;
    if (idx >= total) return;
    int i  = idx & 31;
    int t  = (idx >> 5) & (TT - 1);
    int bh = idx >> 16;
    int ti = (idx & 0xFFFF);
    float sn = g_rope_s[ti], cs = g_rope_c[ti];
    float* p = buf + ((size_t)bh * TT + t) * 64;
    float x1 = p[i], x2 = p[i + 32];
    p[i]      = tf32r(x1 * cs - x2 * sn);
    p[i + 32] = tf32r(x2 * cs + x1 * sn);
}

// ---------------- sliding-window flash attention ----------------
#define PITCH 65
__global__ __launch_bounds__(256) void attn_k(const float* __restrict__ q,
                                              const float* __restrict__ k,
                                              const float* __restrict__ v,
                                              float* __restrict__ O) {
    extern __shared__ float sma[];
    float* Qs = sma;                      // 64*65
    float* Ks = Qs + 64 * PITCH;
    float* Vs = Ks + 64 * PITCH;
    float* Ss = Vs + 64 * PITCH;
    float* m_s  = Ss + 64 * PITCH;
    float* l_s  = m_s + 64;
    float* al_s = l_s + 64;

    const int qt = blockIdx.x, hq = blockIdx.y, b = blockIdx.z;
    const int hk = hq & (NKV - 1);
    const int tid = threadIdx.x;
    const int q0 = qt * 64;
    const float* qb = q + (((size_t)(b * NHQ + hq)) * TT + q0) * 64;
    const float* kb = k + ((size_t)(b * NKV + hk)) * TT * 64;
    const float* vb = v + ((size_t)(b * NKV + hk)) * TT * 64;

    {
        int r = tid >> 2, cg = (tid & 3) * 16;
        #pragma unroll
        for (int g = 0; g < 16; g += 4) {
            float4 t4 = *(const float4*)(qb + (size_t)r * 64 + cg + g);
            Qs[r * PITCH + cg + g + 0] = t4.x; Qs[r * PITCH + cg + g + 1] = t4.y;
            Qs[r * PITCH + cg + g + 2] = t4.z; Qs[r * PITCH + cg + g + 3] = t4.w;
        }
    }
    if (tid < 64) { m_s[tid] = -1e30f; l_s[tid] = 0.f; }

    const int tr = tid >> 4, tc = tid & 15;
    const int r0 = tr * 4, c0 = tc * 4;
    float o[4][4];
    #pragma unroll
    for (int i = 0; i < 4; i++)
        #pragma unroll
        for (int j = 0; j < 4; j++) o[i][j] = 0.f;

    int kb_lo = max(0, q0 - (WIN - 1)) >> 6;
    for (int kbi = kb_lo; kbi <= qt; kbi++) {
        int j0 = kbi * 64;
        __syncthreads();
        {
            int r = tid >> 2, cg = (tid & 3) * 16;
            #pragma unroll
            for (int g = 0; g < 16; g += 4) {
                float4 t4 = *(const float4*)(kb + ((size_t)(j0 + r)) * 64 + cg + g);
                Ks[r * PITCH + cg + g + 0] = t4.x; Ks[r * PITCH + cg + g + 1] = t4.y;
                Ks[r * PITCH + cg + g + 2] = t4.z; Ks[r * PITCH + cg + g + 3] = t4.w;
                float4 u4 = *(const float4*)(vb + ((size_t)(j0 + r)) * 64 + cg + g);
                Vs[r * PITCH + cg + g + 0] = u4.x; Vs[r * PITCH + cg + g + 1] = u4.y;
                Vs[r * PITCH + cg + g + 2] = u4.z; Vs[r * PITCH + cg + g + 3] = u4.w;
            }
        }
        __syncthreads();

        float sreg[4][4];
        #pragma unroll
        for (int i = 0; i < 4; i++)
            #pragma unroll
            for (int j = 0; j < 4; j++) sreg[i][j] = 0.f;
        #pragma unroll 8
        for (int kk = 0; kk < 64; kk++) {
            float qv[4], kv[4];
            #pragma unroll
            for (int i = 0; i < 4; i++) qv[i] = Qs[(r0 + i) * PITCH + kk];
            #pragma unroll
            for (int j = 0; j < 4; j++) kv[j] = Ks[(c0 + j) * PITCH + kk];
            #pragma unroll
            for (int i = 0; i < 4; i++)
                #pragma unroll
                for (int j = 0; j < 4; j++) sreg[i][j] += qv[i] * kv[j];
        }
        #pragma unroll
        for (int i = 0; i < 4; i++) {
            int sa = q0 + r0 + i;
            #pragma unroll
            for (int j = 0; j < 4; j++) {
                int ja = j0 + c0 + j;
                float val = sreg[i][j] * 0.125f * 0.02f;
                float th;
                asm("tanh.approx.f32 %0, %1;" : "=f"(th) : "f"(val));
                val = 50.f * th;
                bool valid = (ja <= sa) && (sa - ja < WIN);
                Ss[(r0 + i) * PITCH + (c0 + j)] = valid ? val : -1e30f;
            }
        }
        __syncthreads();

        if (tid < 64) {
            float mold = m_s[tid];
            float mx = mold;
            float* srow = Ss + tid * PITCH;
            #pragma unroll 8
            for (int c2 = 0; c2 < 64; c2++) mx = fmaxf(mx, srow[c2]);
            if (mx < -1e29f) {
                al_s[tid] = 1.f;
                #pragma unroll 8
                for (int c2 = 0; c2 < 64; c2++) srow[c2] = 0.f;
            } else {
                float al = __expf(mold - mx);
                float ls = 0.f;
                #pragma unroll 8
                for (int c2 = 0; c2 < 64; c2++) {
                    float p = __expf(srow[c2] - mx);
                    srow[c2] = p; ls += p;
                }
                l_s[tid] = l_s[tid] * al + ls;
                m_s[tid] = mx;
                al_s[tid] = al;
            }
        }
        __syncthreads();

        #pragma unroll
        for (int i = 0; i < 4; i++) {
            float al = al_s[r0 + i];
            #pragma unroll
            for (int j = 0; j < 4; j++) o[i][j] *= al;
        }
        #pragma unroll 8
        for (int kk = 0; kk < 64; kk++) {
            float vv0 = Vs[kk * PITCH + c0 + 0];
            float vv1 = Vs[kk * PITCH + c0 + 1];
            float vv2 = Vs[kk * PITCH + c0 + 2];
            float vv3 = Vs[kk * PITCH + c0 + 3];
            #pragma unroll
            for (int i = 0; i < 4; i++) {
                float p = Ss[(r0 + i) * PITCH + kk];
                o[i][0] += p * vv0; o[i][1] += p * vv1;
                o[i][2] += p * vv2; o[i][3] += p * vv3;
            }
        }
    }

    #pragma unroll
    for (int i = 0; i < 4; i++) {
        float invl = 1.f / l_s[r0 + i];
        size_t base = ((size_t)(b * TT + q0 + r0 + i)) * CCH + hq * 64 + c0;
        #pragma unroll
        for (int j = 0; j < 4; j++) O[base + j] = tf32r(o[i][j] * invl);
    }
}

// ---------------- excess kurtosis ----------------
__global__ __launch_bounds__(256) void kurt_rows_k(const float* __restrict__ x,
                                                   float* __restrict__ rowk) {
    int row = blockIdx.x;
    const float* xr = x + (size_t)row * CCH;
    float s = 0.f;
    for (int i = threadIdx.x; i < CCH; i += 256) s += xr[i];
    s = blockReduceSum(s);
    float mean = s / CCH;
    float a2 = 0.f, a4 = 0.f;
    for (int i = threadIdx.x; i < CCH; i += 256) {
        float d = xr[i] - mean; float d2 = d * d;
        a2 += d2; a4 += d2 * d2;
    }
    a2 = blockReduceSum(a2);
    a4 = blockReduceSum(a4);
    if (threadIdx.x == 0) {
        float var = a2 / CCH, m4 = a4 / CCH;
        float kurt = m4 / (var * var + 1e-6f) - 3.f;
        rowk[row] = fmaxf(kurt, 0.f);
    }
}

__global__ __launch_bounds__(256) void kurt_final_k(const float* __restrict__ rowk,
                                                    const float* __restrict__ ksum,
                                                    float* __restrict__ outp) {
    float s = 0.f;
    for (int i = threadIdx.x; i < MROWS; i += 256) s += rowk[i];
    s = blockReduceSum(s);
    if (threadIdx.x == 0) outp[0] = s + ksum[0];
}

// ---------------- launcher ----------------
extern "C" void kernel_launch(void* const* d_in, const int* in_sizes, int n_in,
                              void* d_out, int out_size) {
    (void)in_sizes; (void)n_in; (void)out_size;
    const float* x    = (const float*)d_in[0];
    const float* ksum = (const float*)d_in[1];
    const float* rms1 = (const float*)d_in[2];
    const float* qw   = (const float*)d_in[3];
    const float* kw   = (const float*)d_in[4];
    const float* vw   = (const float*)d_in[5];
    const float* ow   = (const float*)d_in[6];
    const float* rms2 = (const float*)d_in[7];
    const float* gw   = (const float*)d_in[8];
    const float* uw   = (const float*)d_in[9];
    const float* dw   = (const float*)d_in[10];
    float* out = (float*)d_out;

    float *attn_in, *qb, *kb, *vb, *Ob, *x1, *mlp, *hb, *rowk, *wc;
    cudaGetSymbolAddress((void**)&attn_in, g_attn_in);
    cudaGetSymbolAddress((void**)&qb,   g_q);
    cudaGetSymbolAddress((void**)&kb,   g_k);
    cudaGetSymbolAddress((void**)&vb,   g_v);
    cudaGetSymbolAddress((void**)&Ob,   g_O);
    cudaGetSymbolAddress((void**)&x1,   g_x1);
    cudaGetSymbolAddress((void**)&mlp,  g_mlp);
    cudaGetSymbolAddress((void**)&hb,   g_h);
    cudaGetSymbolAddress((void**)&rowk, g_rowk);
    cudaGetSymbolAddress((void**)&wc,   g_wc);

    float* qw2 = wc + OFF_QW;  float* kw2 = wc + OFF_KW;
    float* vw2 = wc + OFF_VW;  float* ow2 = wc + OFF_OW;
    float* gw2 = wc + OFF_GW;  float* uw2 = wc + OFF_UW;
    float* dw2 = wc + OFF_DW;

    cudaFuncSetAttribute(tgemm_k,    cudaFuncAttributeMaxDynamicSharedMemorySize, GEMM_SMEM);
    cudaFuncSetAttribute(tgemm_gu_k, cudaFuncAttributeMaxDynamicSharedMemorySize, GU_SMEM);

    // 0) weight prep (transpose [K,N]->[N,K] + tf32 round) + rope table
    dim3 tb(32, 8);
    wprep_k<<<dim3(1024/32, 1024/32), tb>>>(qw, qw2, 1024, 1024);
    wprep_k<<<dim3(512/32,  1024/32), tb>>>(kw, kw2, 1024, 512);
    wprep_k<<<dim3(512/32,  1024/32), tb>>>(vw, vw2, 1024, 512);
    wprep_k<<<dim3(1024/32, 1024/32), tb>>>(ow, ow2, 1024, 1024);
    wprep_k<<<dim3(HID/32,  1024/32), tb>>>(gw, gw2, 1024, HID);
    wprep_k<<<dim3(HID/32,  1024/32), tb>>>(uw, uw2, 1024, HID);
    wprep_k<<<dim3(1024/32, HID/32),  tb>>>(dw, dw2, HID, 1024);
    rope_table_k<<<(TT * 32) / 256, 256>>>();

    // 1) rmsnorm1 (tf32-rounded out)
    rmsnorm_k<<<MROWS, 256>>>(x, rms1, attn_in);

    // 2) QKV projections
    dim3 gq(1024 / 128, MROWS / 128);
    tgemm_k<<<gq, 256, GEMM_SMEM>>>(attn_in, qw2, qb, MROWS, 1024, CCH, 1, nullptr, TT, NHQ);
    dim3 gkv(512 / 128, MROWS / 128);
    tgemm_k<<<gkv, 256, GEMM_SMEM>>>(attn_in, kw2, kb, MROWS, 512, CCH, 1, nullptr, TT, NKV);
    tgemm_k<<<gkv, 256, GEMM_SMEM>>>(attn_in, vw2, vb, MROWS, 512, CCH, 1, nullptr, TT, NKV);

    // 3) RoPE
    int nq = BB * NHQ * TT * 32;
    rope_k<<<nq / 256, 256>>>(qb, nq);
    int nk = BB * NKV * TT * 32;
    rope_k<<<nk / 256, 256>>>(kb, nk);

    // 4) attention
    int smemAttn = (4 * 64 * PITCH + 3 * 64) * (int)sizeof(float);
    cudaFuncSetAttribute(attn_k, cudaFuncAttributeMaxDynamicSharedMemorySize, smemAttn);
    dim3 ga(TT / 64, NHQ, BB);
    attn_k<<<ga, 256, smemAttn>>>(qb, kb, vb, Ob);

    // 5) out projection + residual
    dim3 go(CCH / 128, MROWS / 128);
    tgemm_k<<<go, 256, GEMM_SMEM>>>(Ob, ow2, x1, MROWS, CCH, 1024, 2, x, 0, 0);

    // 6) rmsnorm2
    rmsnorm_k<<<MROWS, 256>>>(x1, rms2, mlp);

    // 7) MLP: fused gate+up, then down + residual (writes straight to d_out)
    dim3 gg(HID / 128, MROWS / 128);
    tgemm_gu_k<<<gg, 256, GU_SMEM>>>(mlp, gw2, uw2, hb, MROWS, HID, CCH);
    dim3 gd(CCH / 128, MROWS / 128);
    tgemm_k<<<gd, 256, GEMM_SMEM>>>(hb, dw2, out, MROWS, CCH, HID, 2, x1, 0, 0);

    // 8) kurtosis
    kurt_rows_k<<<MROWS, 256>>>(out, rowk);
    kurt_final_k<<<1, 256>>>(rowk, ksum, out + (size_t)MROWS * CCH);
}